// round 1
// baseline (speedup 1.0000x reference)
#include <cuda_runtime.h>
#include <math.h>
#include <stdint.h>

#define BATCH 4
#define CCH   64
#define NN    4096
#define HH    64
#define WWID  64
#define DQK   8
#define FCH   16
#define BI    64
#define BJ    64

// ---------------- scratch (static device globals; no allocs allowed) ----------
__device__ float g_q [BATCH*DQK*NN];
__device__ float g_k [BATCH*DQK*NN];
__device__ float g_v [BATCH*CCH*NN];
__device__ float g_y1[BATCH*FCH*NN];        // after 1x1 conv
__device__ float g_y2[BATCH*FCH*20*20];     // after softpool
__device__ float g_y3[BATCH*FCH*10*10];     // after 3x3 s2 conv
__device__ float g_y4[BATCH*CCH*10*10];     // after 3x3 conv + sigmoid
__device__ float g_mod[BATCH*CCH*NN];       // upsample(w) * gate

// ---------------- kernel 1: fused 1x1 convs (q,k,v,y1) ------------------------
// 96 output channels: [0:8)=q, [8:16)=k, [16:80)=v, [80:96)=y1
__global__ __launch_bounds__(256) void qkv_kernel(
    const float* __restrict__ x,
    const float* __restrict__ qw, const float* __restrict__ qb,
    const float* __restrict__ kw, const float* __restrict__ kb,
    const float* __restrict__ vw, const float* __restrict__ vb,
    const float* __restrict__ w1, const float* __restrict__ b1)
{
    __shared__ float Ws[96*64];
    __shared__ float bs[96];
    __shared__ float xs[64*64];   // [c][n] tile of 64 n

    const int b  = blockIdx.y;
    const int n0 = blockIdx.x * 64;
    const int t  = threadIdx.x;

    for (int i = t; i < 512;  i += 256) Ws[i]        = qw[i];
    for (int i = t; i < 512;  i += 256) Ws[512 + i]  = kw[i];
    for (int i = t; i < 4096; i += 256) Ws[1024 + i] = vw[i];
    for (int i = t; i < 1024; i += 256) Ws[5120 + i] = w1[i];
    if (t < 96) {
        float bv;
        if      (t < 8)  bv = qb[t];
        else if (t < 16) bv = kb[t-8];
        else if (t < 80) bv = vb[t-16];
        else             bv = b1[t-80];
        bs[t] = bv;
    }
    // x tile: 64 c x 64 n, float4-coalesced
    #pragma unroll
    for (int kk = 0; kk < 4; kk++) {
        int idx4 = t + 256*kk;          // 1024 float4
        int c = idx4 >> 4, n4 = idx4 & 15;
        float4 v = *((const float4*)(x + ((size_t)b*CCH + c)*NN + n0) + n4);
        *((float4*)(xs + c*64) + n4) = v;
    }
    __syncthreads();

    const int n = t & 63;
    const int g = t >> 6;               // 0..3, 24 oc each
    const int gn = n0 + n;
    for (int k = 0; k < 24; k++) {
        int oc = g*24 + k;
        const float* wr = Ws + oc*64;
        float acc = bs[oc];
        #pragma unroll 8
        for (int c = 0; c < 64; c++) acc += wr[c] * xs[c*64 + n];
        if      (oc < 8)  g_q[((size_t)b*DQK + oc     )*NN + gn] = acc;
        else if (oc < 16) g_k[((size_t)b*DQK + oc - 8 )*NN + gn] = acc;
        else if (oc < 80) g_v[((size_t)b*CCH + oc - 16)*NN + gn] = acc;
        else              g_y1[((size_t)b*FCH + oc - 80)*NN + gn] = acc;
    }
}

// ---------------- kernel 2: softpool 7x7 stride 3 ------------------------------
__global__ void softpool_kernel()
{
    int idx = blockIdx.x*blockDim.x + threadIdx.x;     // 4*16*20*20 = 25600
    if (idx >= BATCH*FCH*400) return;
    int ox = idx % 20, oy = (idx/20) % 20;
    int c  = (idx/400) % FCH, b = idx/(400*FCH);
    const float* src = g_y1 + ((size_t)b*FCH + c)*NN + (oy*3)*WWID + ox*3;
    float num = 0.f, den = 0.f;
    #pragma unroll
    for (int ky = 0; ky < 7; ky++)
        #pragma unroll
        for (int kx = 0; kx < 7; kx++) {
            float v = src[ky*WWID + kx];
            float e = __expf(v);
            num += e*v; den += e;
        }
    g_y2[idx] = num/den;    // (sum e*x /49)/(sum e /49) = num/den
}

// ---------------- kernel 3: 3x3 conv stride 2 pad 1 (16->16) -------------------
__global__ void conv2_kernel(const float* __restrict__ w2, const float* __restrict__ b2)
{
    int idx = blockIdx.x*blockDim.x + threadIdx.x;     // 4*16*10*10 = 6400
    if (idx >= BATCH*FCH*100) return;
    int ox = idx % 10, oy = (idx/10) % 10;
    int oc = (idx/100) % FCH, b = idx/(100*FCH);
    float acc = b2[oc];
    for (int ic = 0; ic < FCH; ic++) {
        const float* src = g_y2 + ((size_t)b*FCH + ic)*400;
        const float* wr  = w2 + (oc*FCH + ic)*9;
        #pragma unroll
        for (int ky = 0; ky < 3; ky++) {
            int iy = oy*2 - 1 + ky;
            if (iy < 0 || iy >= 20) continue;
            #pragma unroll
            for (int kx = 0; kx < 3; kx++) {
                int ix = ox*2 - 1 + kx;
                if (ix < 0 || ix >= 20) continue;
                acc += wr[ky*3+kx] * src[iy*20 + ix];
            }
        }
    }
    g_y3[idx] = acc;
}

// ---------------- kernel 4: 3x3 conv pad 1 (16->64) + sigmoid ------------------
__global__ void conv3_kernel(const float* __restrict__ w3, const float* __restrict__ b3)
{
    int idx = blockIdx.x*blockDim.x + threadIdx.x;     // 4*64*10*10 = 25600
    if (idx >= BATCH*CCH*100) return;
    int ox = idx % 10, oy = (idx/10) % 10;
    int oc = (idx/100) % CCH, b = idx/(100*CCH);
    float acc = b3[oc];
    for (int ic = 0; ic < FCH; ic++) {
        const float* src = g_y3 + ((size_t)b*FCH + ic)*100;
        const float* wr  = w3 + (oc*FCH + ic)*9;
        #pragma unroll
        for (int ky = 0; ky < 3; ky++) {
            int iy = oy - 1 + ky;
            if (iy < 0 || iy >= 10) continue;
            #pragma unroll
            for (int kx = 0; kx < 3; kx++) {
                int ix = ox - 1 + kx;
                if (ix < 0 || ix >= 10) continue;
                acc += wr[ky*3+kx] * src[iy*10 + ix];
            }
        }
    }
    g_y4[idx] = 1.f/(1.f + __expf(-acc));
}

// ---------------- kernel 5: bilinear upsample 10->64 (* gate) ------------------
__global__ void mod_kernel(const float* __restrict__ x)
{
    int idx = blockIdx.x*blockDim.x + threadIdx.x;     // 4*64*64*64 = 2^22
    int w = idx & 63, h = (idx >> 6) & 63, c = (idx >> 12) & 63, b = idx >> 18;
    // half-pixel sampling; out-of-range weights renormalize == index clamp
    float sy = (h + 0.5f)*(10.0f/64.0f) - 0.5f;
    float sx = (w + 0.5f)*(10.0f/64.0f) - 0.5f;
    int y0 = (int)floorf(sy); float fy = sy - (float)y0;
    int x0 = (int)floorf(sx); float fx = sx - (float)x0;
    int y0c = max(y0, 0),   y1c = min(y0+1, 9);
    int x0c = max(x0, 0),   x1c = min(x0+1, 9);
    const float* src = g_y4 + ((size_t)b*CCH + c)*100;
    float v00 = src[y0c*10 + x0c], v01 = src[y0c*10 + x1c];
    float v10 = src[y1c*10 + x0c], v11 = src[y1c*10 + x1c];
    float vi = (1.f-fy)*((1.f-fx)*v00 + fx*v01) + fy*((1.f-fx)*v10 + fx*v11);
    float gx = x[(size_t)b*CCH*NN + h*WWID + w];       // channel 0 gate
    float gate = 1.f/(1.f + __expf(-gx));
    g_mod[idx] = vi*gate;
}

// ---------------- kernel 6: flash attention + epilogue -------------------------
// Block: 128 threads, 64 queries x all 64 channels. Thread (ci=t&7, ig=t>>3)
// owns O[ig*4 + r][ci + 8*cc], r<4, cc<8 (strided c -> conflict-free V reads).
__global__ __launch_bounds__(128) void flash_kernel(
    const float* __restrict__ x, const float* __restrict__ gamma_p,
    float* __restrict__ out)
{
    __shared__ float q_s[DQK][BI];
    __shared__ float k_s[DQK][BJ];
    __shared__ float v_s[CCH][BJ+4];   // pitch 68 floats: 16B-aligned rows
    __shared__ float s_s[BI][BJ+1];    // pitch 65: conflict-free scalar access

    const int b  = blockIdx.y;
    const int i0 = blockIdx.x * BI;
    const int t  = threadIdx.x;
    const int ci = t & 7;
    const int ig = t >> 3;
    const int ib = ig * 4;

    for (int k2 = t; k2 < DQK*BI; k2 += 128) {
        int d = k2 >> 6, i = k2 & 63;
        q_s[d][i] = g_q[((size_t)b*DQK + d)*NN + i0 + i];
    }

    float O[4][8];
    float m[4], l[4];
    #pragma unroll
    for (int r = 0; r < 4; r++) {
        m[r] = -1e30f; l[r] = 0.f;
        #pragma unroll
        for (int cc = 0; cc < 8; cc++) O[r][cc] = 0.f;
    }

    for (int jt = 0; jt < NN; jt += BJ) {
        __syncthreads();   // prev O-phase done before overwriting k/v/s
        for (int k2 = t; k2 < DQK*BJ; k2 += 128) {
            int d = k2 >> 6, j = k2 & 63;
            k_s[d][j] = g_k[((size_t)b*DQK + d)*NN + jt + j];
        }
        #pragma unroll
        for (int kk = 0; kk < 8; kk++) {
            int idx4 = t + 128*kk;            // 1024 float4
            int c = idx4 >> 4, j4 = idx4 & 15;
            float4 vv = *(const float4*)(g_v + ((size_t)b*CCH + c)*NN + jt + j4*4);
            *(float4*)(&v_s[c][j4*4]) = vv;
        }
        __syncthreads();

        // ---- S phase: s[r][jj] for i=i0+ib+r, j=ci*8+jj
        float s[4][8];
        #pragma unroll
        for (int r = 0; r < 4; r++)
            #pragma unroll
            for (int jj = 0; jj < 8; jj++) s[r][jj] = 0.f;
        #pragma unroll
        for (int d = 0; d < 8; d++) {
            float4 qv = *(const float4*)(&q_s[d][ib]);
            float4 k0 = *(const float4*)(&k_s[d][ci*8]);
            float4 k1 = *(const float4*)(&k_s[d][ci*8+4]);
            float qq[4] = {qv.x, qv.y, qv.z, qv.w};
            float kk[8] = {k0.x,k0.y,k0.z,k0.w,k1.x,k1.y,k1.z,k1.w};
            #pragma unroll
            for (int r = 0; r < 4; r++)
                #pragma unroll
                for (int jj = 0; jj < 8; jj++)
                    s[r][jj] += qq[r]*kk[jj];
        }
        // ---- online softmax (replicated across the 8 ci lanes sharing i)
        #pragma unroll
        for (int r = 0; r < 4; r++) {
            float mx = s[r][0];
            #pragma unroll
            for (int jj = 1; jj < 8; jj++) mx = fmaxf(mx, s[r][jj]);
            mx = fmaxf(mx, __shfl_xor_sync(0xffffffffu, mx, 1));
            mx = fmaxf(mx, __shfl_xor_sync(0xffffffffu, mx, 2));
            mx = fmaxf(mx, __shfl_xor_sync(0xffffffffu, mx, 4));
            float mnew  = fmaxf(m[r], mx);
            float alpha = __expf(m[r] - mnew);
            float sum = 0.f;
            #pragma unroll
            for (int jj = 0; jj < 8; jj++) {
                float p = __expf(s[r][jj] - mnew);
                s_s[ib+r][ci*8+jj] = p;
                sum += p;
            }
            sum += __shfl_xor_sync(0xffffffffu, sum, 1);
            sum += __shfl_xor_sync(0xffffffffu, sum, 2);
            sum += __shfl_xor_sync(0xffffffffu, sum, 4);
            l[r] = l[r]*alpha + sum;
            m[r] = mnew;
            #pragma unroll
            for (int cc = 0; cc < 8; cc++) O[r][cc] *= alpha;
        }
        __syncthreads();

        // ---- O phase: O[r][cc] += sum_j P[ib+r][j] * V[ci+8cc][j]
        #pragma unroll 2
        for (int j4 = 0; j4 < 16; j4++) {
            float p[4][4];
            #pragma unroll
            for (int r = 0; r < 4; r++)
                #pragma unroll
                for (int jj = 0; jj < 4; jj++)
                    p[r][jj] = s_s[ib+r][j4*4+jj];
            #pragma unroll
            for (int cc = 0; cc < 8; cc++) {
                float4 vv = *(const float4*)(&v_s[ci + 8*cc][j4*4]);
                #pragma unroll
                for (int r = 0; r < 4; r++)
                    O[r][cc] += p[r][0]*vv.x + p[r][1]*vv.y
                              + p[r][2]*vv.z + p[r][3]*vv.w;
            }
        }
    }

    // ---- epilogue: out = gamma*O/l + x*(2 + mod)
    const float gam = *gamma_p;
    #pragma unroll
    for (int r = 0; r < 4; r++) {
        float inv = 1.f / l[r];
        int i = i0 + ib + r;
        #pragma unroll
        for (int cc = 0; cc < 8; cc++) {
            int c = ci + 8*cc;
            size_t off = ((size_t)b*CCH + c)*NN + i;
            float xv = x[off];
            out[off] = gam*O[r][cc]*inv + xv*(2.f + g_mod[off]);
        }
    }
}

// ---------------- launch -------------------------------------------------------
extern "C" void kernel_launch(void* const* d_in, const int* in_sizes, int n_in,
                              void* d_out, int out_size)
{
    const float* x     = (const float*)d_in[0];
    const float* qw    = (const float*)d_in[1];
    const float* qb    = (const float*)d_in[2];
    const float* kw    = (const float*)d_in[3];
    const float* kb    = (const float*)d_in[4];
    const float* vw    = (const float*)d_in[5];
    const float* vb    = (const float*)d_in[6];
    const float* gamma = (const float*)d_in[7];
    const float* w1    = (const float*)d_in[8];
    const float* b1    = (const float*)d_in[9];
    const float* w2    = (const float*)d_in[10];
    const float* b2    = (const float*)d_in[11];
    const float* w3    = (const float*)d_in[12];
    const float* b3    = (const float*)d_in[13];
    float* out = (float*)d_out;

    qkv_kernel<<<dim3(64, BATCH), 256>>>(x, qw, qb, kw, kb, vw, vb, w1, b1);
    softpool_kernel<<<100, 256>>>();
    conv2_kernel<<<25, 256>>>(w2, b2);
    conv3_kernel<<<100, 256>>>(w3, b3);
    mod_kernel<<<4096, 256>>>(x);
    flash_kernel<<<dim3(NN/BI, BATCH), 128>>>(x, gamma, out);
}

// round 3
// speedup vs baseline: 1.3982x; 1.3982x over previous
#include <cuda_runtime.h>
#include <math.h>
#include <stdint.h>

#define BATCH 4
#define CCH   64
#define NN    4096
#define DQK   8
#define FCH   16

// ---------------- scratch ------------------------------------------------------
__device__ float g_q [BATCH*DQK*NN];   // tf32 bits
__device__ float g_k [BATCH*DQK*NN];   // tf32 bits
__device__ float g_v [BATCH*CCH*NN];   // tf32 bits
__device__ float g_y1[BATCH*FCH*NN];   // fp32
__device__ float g_y4[BATCH*CCH*100];  // fp32 sigmoid weights (10x10)

__device__ __forceinline__ float to_tf32(float x){
    uint32_t r;
    asm("cvt.rna.tf32.f32 %0, %1;" : "=r"(r) : "f"(x));
    return __uint_as_float(r);
}
__device__ __forceinline__ void mma_tf32(
    float& d0, float& d1, float& d2, float& d3,
    uint32_t a0, uint32_t a1, uint32_t a2, uint32_t a3,
    uint32_t b0, uint32_t b1)
{
    asm volatile(
        "mma.sync.aligned.m16n8k8.row.col.f32.tf32.tf32.f32 "
        "{%0,%1,%2,%3},{%4,%5,%6,%7},{%8,%9},{%0,%1,%2,%3};"
        : "+f"(d0), "+f"(d1), "+f"(d2), "+f"(d3)
        : "r"(a0), "r"(a1), "r"(a2), "r"(a3), "r"(b0), "r"(b1));
}

// ---------------- kernel 1: fused 1x1 convs (q,k,v,y1) -------------------------
__global__ __launch_bounds__(256) void qkv_kernel(
    const float* __restrict__ x,
    const float* __restrict__ qw, const float* __restrict__ qb,
    const float* __restrict__ kw, const float* __restrict__ kb,
    const float* __restrict__ vw, const float* __restrict__ vb,
    const float* __restrict__ w1, const float* __restrict__ b1)
{
    __shared__ float Ws[96*64];
    __shared__ float bs[96];
    __shared__ float xs[64*64];

    const int b  = blockIdx.y;
    const int n0 = blockIdx.x * 64;
    const int t  = threadIdx.x;

    for (int i = t; i < 512;  i += 256) Ws[i]        = qw[i];
    for (int i = t; i < 512;  i += 256) Ws[512 + i]  = kw[i];
    for (int i = t; i < 4096; i += 256) Ws[1024 + i] = vw[i];
    for (int i = t; i < 1024; i += 256) Ws[5120 + i] = w1[i];
    if (t < 96) {
        float bv;
        if      (t < 8)  bv = qb[t];
        else if (t < 16) bv = kb[t-8];
        else if (t < 80) bv = vb[t-16];
        else             bv = b1[t-80];
        bs[t] = bv;
    }
    #pragma unroll
    for (int kk = 0; kk < 4; kk++) {
        int idx4 = t + 256*kk;
        int c = idx4 >> 4, n4 = idx4 & 15;
        float4 v = *((const float4*)(x + ((size_t)b*CCH + c)*NN + n0) + n4);
        *((float4*)(xs + c*64) + n4) = v;
    }
    __syncthreads();

    const int n = t & 63;
    const int g = t >> 6;
    const int gn = n0 + n;
    for (int k = 0; k < 24; k++) {
        int oc = g*24 + k;
        const float* wr = Ws + oc*64;
        float acc = bs[oc];
        #pragma unroll 8
        for (int c = 0; c < 64; c++) acc += wr[c] * xs[c*64 + n];
        if      (oc < 8)  g_q[((size_t)b*DQK + oc     )*NN + gn] = to_tf32(acc);
        else if (oc < 16) g_k[((size_t)b*DQK + oc - 8 )*NN + gn] = to_tf32(acc);
        else if (oc < 80) g_v[((size_t)b*CCH + oc - 16)*NN + gn] = to_tf32(acc);
        else              g_y1[((size_t)b*FCH + oc - 80)*NN + gn] = acc;
    }
}

// ---------------- kernel 2: fused softpool -> conv2 -> conv3+sigmoid -----------
__global__ __launch_bounds__(256) void la_chain_kernel(
    const float* __restrict__ w2, const float* __restrict__ b2,
    const float* __restrict__ w3, const float* __restrict__ b3)
{
    __shared__ float y2s[FCH*400];   // 25.6 KB
    __shared__ float y3s[FCH*100];   // 6.4 KB
    const int b = blockIdx.x;
    const int t = threadIdx.x;

    // softpool 7x7 s3 on g_y1 (64x64 -> 20x20), 16 ch
    for (int o = t; o < FCH*400; o += 256) {
        int ox = o % 20, oy = (o/20) % 20, c = o/400;
        const float* src = g_y1 + ((size_t)b*FCH + c)*NN + (oy*3)*64 + ox*3;
        float num = 0.f, den = 0.f;
        #pragma unroll
        for (int ky = 0; ky < 7; ky++)
            #pragma unroll
            for (int kx = 0; kx < 7; kx++) {
                float v = src[ky*64 + kx];
                float e = __expf(v);
                num += e*v; den += e;
            }
        y2s[o] = num/den;
    }
    __syncthreads();

    // conv2: 3x3 s2 p1, 16->16, 20x20 -> 10x10
    for (int o = t; o < FCH*100; o += 256) {
        int ox = o % 10, oy = (o/10) % 10, oc = o/100;
        float acc = b2[oc];
        for (int ic = 0; ic < FCH; ic++) {
            const float* src = y2s + ic*400;
            const float* wr  = w2 + (oc*FCH + ic)*9;
            #pragma unroll
            for (int ky = 0; ky < 3; ky++) {
                int iy = oy*2 - 1 + ky;
                if (iy < 0 || iy >= 20) continue;
                #pragma unroll
                for (int kx = 0; kx < 3; kx++) {
                    int ix = ox*2 - 1 + kx;
                    if (ix < 0 || ix >= 20) continue;
                    acc += wr[ky*3+kx] * src[iy*20 + ix];
                }
            }
        }
        y3s[o] = acc;
    }
    __syncthreads();

    // conv3: 3x3 p1, 16->64, + sigmoid
    for (int o = t; o < CCH*100; o += 256) {
        int ox = o % 10, oy = (o/10) % 10, oc = o/100;
        float acc = b3[oc];
        for (int ic = 0; ic < FCH; ic++) {
            const float* src = y3s + ic*100;
            const float* wr  = w3 + (oc*FCH + ic)*9;
            #pragma unroll
            for (int ky = 0; ky < 3; ky++) {
                int iy = oy - 1 + ky;
                if (iy < 0 || iy >= 10) continue;
                #pragma unroll
                for (int kx = 0; kx < 3; kx++) {
                    int ix = ox - 1 + kx;
                    if (ix < 0 || ix >= 10) continue;
                    acc += wr[ky*3+kx] * src[iy*10 + ix];
                }
            }
        }
        g_y4[(size_t)b*CCH*100 + o] = 1.f/(1.f + __expf(-acc));
    }
}

// ---------------- kernel 3: tensor-core flash attention + fused epilogue -------
// Block = 64 queries x 64 channels, 4 warps. Warp w owns query rows [16w,16w+16).
// S-phase: mma m16n8k8 (K=d=8, one step). O^T = V * P^T so P is the B operand,
// built from the S C-fragment with intra-quad shuffles (no smem round trip).
__global__ __launch_bounds__(128) void flash_tc_kernel(
    const float* __restrict__ x, const float* __restrict__ gamma_p,
    float* __restrict__ out)
{
    __shared__ float qs[8*72];     // pitch 72: conflict-free fragment loads
    __shared__ float ks[8*72];
    __shared__ float vs[64*68];    // pitch 68; reused as O staging at the end

    const int b  = blockIdx.y;
    const int i0 = blockIdx.x * 64;
    const int t  = threadIdx.x;
    const int w  = t >> 5;
    const int lane = t & 31;
    const int r  = lane >> 2;      // group id
    const int q4 = lane & 3;       // thread in group

    for (int kx = t; kx < 512; kx += 128) {
        int d = kx >> 6, i = kx & 63;
        qs[d*72 + i] = g_q[((size_t)b*DQK + d)*NN + i0 + i];
    }

    float Oa[4][2][4];
    #pragma unroll
    for (int mt = 0; mt < 4; mt++)
        #pragma unroll
        for (int nt = 0; nt < 2; nt++)
            #pragma unroll
            for (int u = 0; u < 4; u++) Oa[mt][nt][u] = 0.f;

    float m_lo = -1e30f, m_hi = -1e30f, l_lo = 0.f, l_hi = 0.f;
    uint32_t aq0=0, aq1=0, aq2=0, aq3=0;

    const int ls0 = (lane & 28) | (q4 >> 1);
    const int e   = lane & 1;

    for (int jt = 0; jt < NN; jt += 64) {
        __syncthreads();
        for (int kx = t; kx < 512; kx += 128) {
            int d = kx >> 6, j = kx & 63;
            ks[d*72 + j] = g_k[((size_t)b*DQK + d)*NN + jt + j];
        }
        #pragma unroll
        for (int kk = 0; kk < 8; kk++) {
            int idx4 = t + 128*kk;
            int c = idx4 >> 4, j4 = idx4 & 15;
            float4 vv = *(const float4*)(g_v + ((size_t)b*CCH + c)*NN + jt + j4*4);
            *(float4*)&vs[c*68 + j4*4] = vv;
        }
        __syncthreads();

        if (jt == 0) {
            aq0 = __float_as_uint(qs[ q4   *72 + 16*w + r    ]);
            aq1 = __float_as_uint(qs[ q4   *72 + 16*w + r + 8]);
            aq2 = __float_as_uint(qs[(q4+4)*72 + 16*w + r    ]);
            aq3 = __float_as_uint(qs[(q4+4)*72 + 16*w + r + 8]);
        }

        // ---- S = Q*K (16 rows x 64 cols per warp), 8 mma
        float P[8][4];
        #pragma unroll
        for (int t8 = 0; t8 < 8; t8++) {
            uint32_t kb0 = __float_as_uint(ks[ q4   *72 + t8*8 + r]);
            uint32_t kb1 = __float_as_uint(ks[(q4+4)*72 + t8*8 + r]);
            P[t8][0] = P[t8][1] = P[t8][2] = P[t8][3] = 0.f;
            mma_tf32(P[t8][0], P[t8][1], P[t8][2], P[t8][3],
                     aq0, aq1, aq2, aq3, kb0, kb1);
        }

        // ---- online softmax (rows r and r+8)
        float mx_lo = -1e30f, mx_hi = -1e30f;
        #pragma unroll
        for (int t8 = 0; t8 < 8; t8++) {
            mx_lo = fmaxf(mx_lo, fmaxf(P[t8][0], P[t8][1]));
            mx_hi = fmaxf(mx_hi, fmaxf(P[t8][2], P[t8][3]));
        }
        mx_lo = fmaxf(mx_lo, __shfl_xor_sync(0xffffffffu, mx_lo, 1));
        mx_lo = fmaxf(mx_lo, __shfl_xor_sync(0xffffffffu, mx_lo, 2));
        mx_hi = fmaxf(mx_hi, __shfl_xor_sync(0xffffffffu, mx_hi, 1));
        mx_hi = fmaxf(mx_hi, __shfl_xor_sync(0xffffffffu, mx_hi, 2));
        float mn_lo = fmaxf(m_lo, mx_lo), mn_hi = fmaxf(m_hi, mx_hi);
        float al_lo = __expf(m_lo - mn_lo), al_hi = __expf(m_hi - mn_hi);
        m_lo = mn_lo; m_hi = mn_hi;
        float s_lo = 0.f, s_hi = 0.f;
        #pragma unroll
        for (int t8 = 0; t8 < 8; t8++) {
            P[t8][0] = __expf(P[t8][0] - m_lo); s_lo += P[t8][0];
            P[t8][1] = __expf(P[t8][1] - m_lo); s_lo += P[t8][1];
            P[t8][2] = __expf(P[t8][2] - m_hi); s_hi += P[t8][2];
            P[t8][3] = __expf(P[t8][3] - m_hi); s_hi += P[t8][3];
        }
        s_lo += __shfl_xor_sync(0xffffffffu, s_lo, 1);
        s_lo += __shfl_xor_sync(0xffffffffu, s_lo, 2);
        s_hi += __shfl_xor_sync(0xffffffffu, s_hi, 1);
        s_hi += __shfl_xor_sync(0xffffffffu, s_hi, 2);
        l_lo = l_lo*al_lo + s_lo;
        l_hi = l_hi*al_hi + s_hi;

        // ---- rescale O^T by alpha, indexed by column i' = 2*q4(+1) (+8 for nt1)
        float a0lo = __shfl_sync(0xffffffffu, al_lo, 8*q4);
        float a1lo = __shfl_sync(0xffffffffu, al_lo, 8*q4 + 4);
        float a0hi = __shfl_sync(0xffffffffu, al_hi, 8*q4);
        float a1hi = __shfl_sync(0xffffffffu, al_hi, 8*q4 + 4);
        #pragma unroll
        for (int mt = 0; mt < 4; mt++) {
            Oa[mt][0][0] *= a0lo; Oa[mt][0][1] *= a1lo;
            Oa[mt][0][2] *= a0lo; Oa[mt][0][3] *= a1lo;
            Oa[mt][1][0] *= a0hi; Oa[mt][1][1] *= a1hi;
            Oa[mt][1][2] *= a0hi; Oa[mt][1][3] *= a1hi;
        }

        // ---- O^T += V * P^T : per jc build B-frags from P via quad shuffles
        #pragma unroll
        for (int jc = 0; jc < 8; jc++) {
            float p0a = __shfl_sync(0xffffffffu, P[jc][0], ls0);
            float p0b = __shfl_sync(0xffffffffu, P[jc][1], ls0);
            float p1a = __shfl_sync(0xffffffffu, P[jc][0], ls0 + 2);
            float p1b = __shfl_sync(0xffffffffu, P[jc][1], ls0 + 2);
            uint32_t bn0_0 = __float_as_uint(e ? p0b : p0a);
            uint32_t bn0_1 = __float_as_uint(e ? p1b : p1a);
            float p2a = __shfl_sync(0xffffffffu, P[jc][2], ls0);
            float p2b = __shfl_sync(0xffffffffu, P[jc][3], ls0);
            float p3a = __shfl_sync(0xffffffffu, P[jc][2], ls0 + 2);
            float p3b = __shfl_sync(0xffffffffu, P[jc][3], ls0 + 2);
            uint32_t bn1_0 = __float_as_uint(e ? p2b : p2a);
            uint32_t bn1_1 = __float_as_uint(e ? p3b : p3a);
            #pragma unroll
            for (int mt = 0; mt < 4; mt++) {
                const float* vr = &vs[(16*mt + r)*68 + 8*jc + q4];
                uint32_t a0 = __float_as_uint(vr[0]);
                uint32_t a1 = __float_as_uint(vr[8*68]);
                uint32_t a2 = __float_as_uint(vr[4]);
                uint32_t a3 = __float_as_uint(vr[8*68 + 4]);
                mma_tf32(Oa[mt][0][0], Oa[mt][0][1], Oa[mt][0][2], Oa[mt][0][3],
                         a0, a1, a2, a3, bn0_0, bn0_1);
                mma_tf32(Oa[mt][1][0], Oa[mt][1][1], Oa[mt][1][2], Oa[mt][1][3],
                         a0, a1, a2, a3, bn1_0, bn1_1);
            }
        }
    }

    // ---- finalize: O /= l (column-indexed), stage O^T[c][i_local] in vs
    {
        float il_lo = 1.f / l_lo, il_hi = 1.f / l_hi;
        float i0lo = __shfl_sync(0xffffffffu, il_lo, 8*q4);
        float i1lo = __shfl_sync(0xffffffffu, il_lo, 8*q4 + 4);
        float i0hi = __shfl_sync(0xffffffffu, il_hi, 8*q4);
        float i1hi = __shfl_sync(0xffffffffu, il_hi, 8*q4 + 4);
        #pragma unroll
        for (int mt = 0; mt < 4; mt++) {
            Oa[mt][0][0] *= i0lo; Oa[mt][0][1] *= i1lo;
            Oa[mt][0][2] *= i0lo; Oa[mt][0][3] *= i1lo;
            Oa[mt][1][0] *= i0hi; Oa[mt][1][1] *= i1hi;
            Oa[mt][1][2] *= i0hi; Oa[mt][1][3] *= i1hi;
        }
    }
    __syncthreads();
    #pragma unroll
    for (int mt = 0; mt < 4; mt++) {
        int crow = 16*mt + r;
        int ib = 16*w + 2*q4;
        vs[ crow   *68 + ib    ] = Oa[mt][0][0];
        vs[ crow   *68 + ib + 1] = Oa[mt][0][1];
        vs[(crow+8)*68 + ib    ] = Oa[mt][0][2];
        vs[(crow+8)*68 + ib + 1] = Oa[mt][0][3];
        vs[ crow   *68 + ib + 8] = Oa[mt][1][0];
        vs[ crow   *68 + ib + 9] = Oa[mt][1][1];
        vs[(crow+8)*68 + ib + 8] = Oa[mt][1][2];
        vs[(crow+8)*68 + ib + 9] = Oa[mt][1][3];
    }
    __syncthreads();

    // ---- epilogue: out = gamma*O + x*(2 + bilinear(y4)*sigmoid(x_ch0))
    const float gam = gamma_p[0];
    const int h = blockIdx.x;                 // i0 = h*64, one image row per block
    float sy = (h + 0.5f)*0.15625f - 0.5f;
    int   y0 = (int)floorf(sy);
    float fy = sy - (float)y0;
    int   y0c = max(y0, 0), y1c = min(y0 + 1, 9);

    #pragma unroll
    for (int kk = 0; kk < 8; kk++) {
        int idx4 = t + 128*kk;               // 1024 float4
        int c = idx4 >> 4, k4 = (idx4 & 15)*4;
        const float* yr0 = g_y4 + ((size_t)b*CCH + c)*100 + y0c*10;
        const float* yr1 = g_y4 + ((size_t)b*CCH + c)*100 + y1c*10;
        size_t off = ((size_t)b*CCH + c)*NN + i0 + k4;
        float4 xv = *(const float4*)(x + off);
        float4 g4 = *(const float4*)(x + (size_t)b*CCH*NN + i0 + k4);  // ch 0
        float xa[4] = {xv.x, xv.y, xv.z, xv.w};
        float ga[4] = {g4.x, g4.y, g4.z, g4.w};
        float res[4];
        #pragma unroll
        for (int u = 0; u < 4; u++) {
            int wpix = k4 + u;
            float sx = (wpix + 0.5f)*0.15625f - 0.5f;
            int   x0i = (int)floorf(sx);
            float fx = sx - (float)x0i;
            int   x0c = max(x0i, 0), x1c = min(x0i + 1, 9);
            float v00 = yr0[x0c], v01 = yr0[x1c];
            float v10 = yr1[x0c], v11 = yr1[x1c];
            float wv = (1.f-fy)*((1.f-fx)*v00 + fx*v01)
                     +       fy*((1.f-fx)*v10 + fx*v11);
            float gate = 1.f/(1.f + __expf(-ga[u]));
            res[u] = gam*vs[c*68 + k4 + u] + xa[u]*(2.f + wv*gate);
        }
        *(float4*)(out + off) = make_float4(res[0], res[1], res[2], res[3]);
    }
}

// ---------------- launch -------------------------------------------------------
extern "C" void kernel_launch(void* const* d_in, const int* in_sizes, int n_in,
                              void* d_out, int out_size)
{
    const float* x     = (const float*)d_in[0];
    const float* qw    = (const float*)d_in[1];
    const float* qb    = (const float*)d_in[2];
    const float* kw    = (const float*)d_in[3];
    const float* kb    = (const float*)d_in[4];
    const float* vw    = (const float*)d_in[5];
    const float* vb    = (const float*)d_in[6];
    const float* gamma = (const float*)d_in[7];
    const float* w1    = (const float*)d_in[8];
    const float* b1    = (const float*)d_in[9];
    const float* w2    = (const float*)d_in[10];
    const float* b2    = (const float*)d_in[11];
    const float* w3    = (const float*)d_in[12];
    const float* b3    = (const float*)d_in[13];
    float* out = (float*)d_out;

    qkv_kernel<<<dim3(64, BATCH), 256>>>(x, qw, qb, kw, kb, vw, vb, w1, b1);
    la_chain_kernel<<<BATCH, 256>>>(w2, b2, w3, b3);
    flash_tc_kernel<<<dim3(64, BATCH), 128>>>(x, gamma, out);
}

// round 4
// speedup vs baseline: 1.4857x; 1.0626x over previous
#include <cuda_runtime.h>
#include <math.h>
#include <stdint.h>

#define BATCH 4
#define CCH   64
#define NN    4096
#define DQK   8
#define FCH   16

// ---------------- scratch ------------------------------------------------------
__device__ float g_q [BATCH*DQK*NN];   // tf32 bits
__device__ float g_k [BATCH*DQK*NN];   // tf32 bits
__device__ float g_v [BATCH*CCH*NN];   // tf32 bits
__device__ float g_e [BATCH*FCH*NN];   // exp(y1)
__device__ float g_ev[BATCH*FCH*NN];   // exp(y1)*y1
__device__ float g_y2[BATCH*FCH*400];  // softpool out (20x20)
__device__ float g_y4[BATCH*CCH*100];  // sigmoid weights (10x10)

__device__ __forceinline__ float to_tf32(float x){
    uint32_t r;
    asm("cvt.rna.tf32.f32 %0, %1;" : "=r"(r) : "f"(x));
    return __uint_as_float(r);
}
__device__ __forceinline__ void mma_tf32(
    float& d0, float& d1, float& d2, float& d3,
    uint32_t a0, uint32_t a1, uint32_t a2, uint32_t a3,
    uint32_t b0, uint32_t b1)
{
    asm volatile(
        "mma.sync.aligned.m16n8k8.row.col.f32.tf32.tf32.f32 "
        "{%0,%1,%2,%3},{%4,%5,%6,%7},{%8,%9},{%0,%1,%2,%3};"
        : "+f"(d0), "+f"(d1), "+f"(d2), "+f"(d3)
        : "r"(a0), "r"(a1), "r"(a2), "r"(a3), "r"(b0), "r"(b1));
}

// ---------------- kernel 1: fused 1x1 convs (q,k,v,y1->e,ev) -------------------
__global__ __launch_bounds__(256) void qkv_kernel(
    const float* __restrict__ x,
    const float* __restrict__ qw, const float* __restrict__ qb,
    const float* __restrict__ kw, const float* __restrict__ kb,
    const float* __restrict__ vw, const float* __restrict__ vb,
    const float* __restrict__ w1, const float* __restrict__ b1)
{
    __shared__ float Ws[96*64];
    __shared__ float bs[96];
    __shared__ float xs[64*64];

    const int b  = blockIdx.y;
    const int n0 = blockIdx.x * 64;
    const int t  = threadIdx.x;

    for (int i = t; i < 512;  i += 256) Ws[i]        = qw[i];
    for (int i = t; i < 512;  i += 256) Ws[512 + i]  = kw[i];
    for (int i = t; i < 4096; i += 256) Ws[1024 + i] = vw[i];
    for (int i = t; i < 1024; i += 256) Ws[5120 + i] = w1[i];
    if (t < 96) {
        float bv;
        if      (t < 8)  bv = qb[t];
        else if (t < 16) bv = kb[t-8];
        else if (t < 80) bv = vb[t-16];
        else             bv = b1[t-80];
        bs[t] = bv;
    }
    #pragma unroll
    for (int kk = 0; kk < 4; kk++) {
        int idx4 = t + 256*kk;
        int c = idx4 >> 4, n4 = idx4 & 15;
        float4 v = *((const float4*)(x + ((size_t)b*CCH + c)*NN + n0) + n4);
        *((float4*)(xs + c*64) + n4) = v;
    }
    __syncthreads();

    const int n = t & 63;
    const int g = t >> 6;
    const int gn = n0 + n;
    for (int k = 0; k < 24; k++) {
        int oc = g*24 + k;
        const float* wr = Ws + oc*64;
        float acc = bs[oc];
        #pragma unroll 8
        for (int c = 0; c < 64; c++) acc += wr[c] * xs[c*64 + n];
        if      (oc < 8)  g_q[((size_t)b*DQK + oc     )*NN + gn] = to_tf32(acc);
        else if (oc < 16) g_k[((size_t)b*DQK + oc - 8 )*NN + gn] = to_tf32(acc);
        else if (oc < 80) g_v[((size_t)b*CCH + oc - 16)*NN + gn] = to_tf32(acc);
        else {
            float e = __expf(acc);
            size_t o = ((size_t)b*FCH + oc - 80)*NN + gn;
            g_e [o] = e;
            g_ev[o] = e*acc;
        }
    }
}

// ---------------- kernel 2: softpool = sum49(ev)/sum49(e) ----------------------
__global__ void softpool_kernel()
{
    int idx = blockIdx.x*blockDim.x + threadIdx.x;     // 25600
    if (idx >= BATCH*FCH*400) return;
    int ox = idx % 20, oy = (idx/20) % 20;
    int c  = (idx/400) % FCH, b = idx/(400*FCH);
    size_t base = ((size_t)b*FCH + c)*NN + (oy*3)*64 + ox*3;
    const float* se  = g_e  + base;
    const float* sev = g_ev + base;
    float num = 0.f, den = 0.f;
    #pragma unroll
    for (int ky = 0; ky < 7; ky++)
        #pragma unroll
        for (int kx = 0; kx < 7; kx++) {
            num += sev[ky*64 + kx];
            den += se [ky*64 + kx];
        }
    g_y2[idx] = num/den;
}

// ---------------- kernel 3: conv2 (3x3 s2 p1) -> conv3 (3x3 p1) + sigmoid ------
__global__ __launch_bounds__(256) void conv23_kernel(
    const float* __restrict__ w2, const float* __restrict__ b2,
    const float* __restrict__ w3, const float* __restrict__ b3)
{
    __shared__ float y2s[FCH*400];
    __shared__ float y3s[FCH*100];
    const int b = blockIdx.x;
    const int t = threadIdx.x;

    for (int o = t; o < FCH*400; o += 256) y2s[o] = g_y2[(size_t)b*FCH*400 + o];
    __syncthreads();

    for (int o = t; o < FCH*100; o += 256) {
        int ox = o % 10, oy = (o/10) % 10, oc = o/100;
        float acc = b2[oc];
        for (int ic = 0; ic < FCH; ic++) {
            const float* src = y2s + ic*400;
            const float* wr  = w2 + (oc*FCH + ic)*9;
            #pragma unroll
            for (int ky = 0; ky < 3; ky++) {
                int iy = oy*2 - 1 + ky;
                if (iy < 0 || iy >= 20) continue;
                #pragma unroll
                for (int kx = 0; kx < 3; kx++) {
                    int ix = ox*2 - 1 + kx;
                    if (ix < 0 || ix >= 20) continue;
                    acc += wr[ky*3+kx] * src[iy*20 + ix];
                }
            }
        }
        y3s[o] = acc;
    }
    __syncthreads();

    for (int o = t; o < CCH*100; o += 256) {
        int ox = o % 10, oy = (o/10) % 10, oc = o/100;
        float acc = b3[oc];
        for (int ic = 0; ic < FCH; ic++) {
            const float* src = y3s + ic*100;
            const float* wr  = w3 + (oc*FCH + ic)*9;
            #pragma unroll
            for (int ky = 0; ky < 3; ky++) {
                int iy = oy - 1 + ky;
                if (iy < 0 || iy >= 10) continue;
                #pragma unroll
                for (int kx = 0; kx < 3; kx++) {
                    int ix = ox - 1 + kx;
                    if (ix < 0 || ix >= 10) continue;
                    acc += wr[ky*3+kx] * src[iy*10 + ix];
                }
            }
        }
        g_y4[(size_t)b*CCH*100 + o] = 1.f/(1.f + __expf(-acc));
    }
}

// ---------------- kernel 4: tensor-core flash attention + fused epilogue -------
__global__ __launch_bounds__(128) void flash_tc_kernel(
    const float* __restrict__ x, const float* __restrict__ gamma_p,
    float* __restrict__ out)
{
    __shared__ float qs[8*72];
    __shared__ float ks[8*72];
    __shared__ float vs[64*68];

    const int b  = blockIdx.y;
    const int i0 = blockIdx.x * 64;
    const int t  = threadIdx.x;
    const int w  = t >> 5;
    const int lane = t & 31;
    const int r  = lane >> 2;
    const int q4 = lane & 3;

    for (int kx = t; kx < 512; kx += 128) {
        int d = kx >> 6, i = kx & 63;
        qs[d*72 + i] = g_q[((size_t)b*DQK + d)*NN + i0 + i];
    }

    float Oa[4][2][4];
    #pragma unroll
    for (int mt = 0; mt < 4; mt++)
        #pragma unroll
        for (int nt = 0; nt < 2; nt++)
            #pragma unroll
            for (int u = 0; u < 4; u++) Oa[mt][nt][u] = 0.f;

    float m_lo = -1e30f, m_hi = -1e30f, l_lo = 0.f, l_hi = 0.f;
    uint32_t aq0=0, aq1=0, aq2=0, aq3=0;

    const int ls0 = (lane & 28) | (q4 >> 1);
    const int e   = lane & 1;

    for (int jt = 0; jt < NN; jt += 64) {
        __syncthreads();
        for (int kx = t; kx < 512; kx += 128) {
            int d = kx >> 6, j = kx & 63;
            ks[d*72 + j] = g_k[((size_t)b*DQK + d)*NN + jt + j];
        }
        #pragma unroll
        for (int kk = 0; kk < 8; kk++) {
            int idx4 = t + 128*kk;
            int c = idx4 >> 4, j4 = idx4 & 15;
            float4 vv = *(const float4*)(g_v + ((size_t)b*CCH + c)*NN + jt + j4*4);
            *(float4*)&vs[c*68 + j4*4] = vv;
        }
        __syncthreads();

        if (jt == 0) {
            aq0 = __float_as_uint(qs[ q4   *72 + 16*w + r    ]);
            aq1 = __float_as_uint(qs[ q4   *72 + 16*w + r + 8]);
            aq2 = __float_as_uint(qs[(q4+4)*72 + 16*w + r    ]);
            aq3 = __float_as_uint(qs[(q4+4)*72 + 16*w + r + 8]);
        }

        float P[8][4];
        #pragma unroll
        for (int t8 = 0; t8 < 8; t8++) {
            uint32_t kb0 = __float_as_uint(ks[ q4   *72 + t8*8 + r]);
            uint32_t kb1 = __float_as_uint(ks[(q4+4)*72 + t8*8 + r]);
            P[t8][0] = P[t8][1] = P[t8][2] = P[t8][3] = 0.f;
            mma_tf32(P[t8][0], P[t8][1], P[t8][2], P[t8][3],
                     aq0, aq1, aq2, aq3, kb0, kb1);
        }

        float mx_lo = -1e30f, mx_hi = -1e30f;
        #pragma unroll
        for (int t8 = 0; t8 < 8; t8++) {
            mx_lo = fmaxf(mx_lo, fmaxf(P[t8][0], P[t8][1]));
            mx_hi = fmaxf(mx_hi, fmaxf(P[t8][2], P[t8][3]));
        }
        mx_lo = fmaxf(mx_lo, __shfl_xor_sync(0xffffffffu, mx_lo, 1));
        mx_lo = fmaxf(mx_lo, __shfl_xor_sync(0xffffffffu, mx_lo, 2));
        mx_hi = fmaxf(mx_hi, __shfl_xor_sync(0xffffffffu, mx_hi, 1));
        mx_hi = fmaxf(mx_hi, __shfl_xor_sync(0xffffffffu, mx_hi, 2));
        float mn_lo = fmaxf(m_lo, mx_lo), mn_hi = fmaxf(m_hi, mx_hi);
        float al_lo = __expf(m_lo - mn_lo), al_hi = __expf(m_hi - mn_hi);
        m_lo = mn_lo; m_hi = mn_hi;
        float s_lo = 0.f, s_hi = 0.f;
        #pragma unroll
        for (int t8 = 0; t8 < 8; t8++) {
            P[t8][0] = __expf(P[t8][0] - m_lo); s_lo += P[t8][0];
            P[t8][1] = __expf(P[t8][1] - m_lo); s_lo += P[t8][1];
            P[t8][2] = __expf(P[t8][2] - m_hi); s_hi += P[t8][2];
            P[t8][3] = __expf(P[t8][3] - m_hi); s_hi += P[t8][3];
        }
        s_lo += __shfl_xor_sync(0xffffffffu, s_lo, 1);
        s_lo += __shfl_xor_sync(0xffffffffu, s_lo, 2);
        s_hi += __shfl_xor_sync(0xffffffffu, s_hi, 1);
        s_hi += __shfl_xor_sync(0xffffffffu, s_hi, 2);
        l_lo = l_lo*al_lo + s_lo;
        l_hi = l_hi*al_hi + s_hi;

        float a0lo = __shfl_sync(0xffffffffu, al_lo, 8*q4);
        float a1lo = __shfl_sync(0xffffffffu, al_lo, 8*q4 + 4);
        float a0hi = __shfl_sync(0xffffffffu, al_hi, 8*q4);
        float a1hi = __shfl_sync(0xffffffffu, al_hi, 8*q4 + 4);
        #pragma unroll
        for (int mt = 0; mt < 4; mt++) {
            Oa[mt][0][0] *= a0lo; Oa[mt][0][1] *= a1lo;
            Oa[mt][0][2] *= a0lo; Oa[mt][0][3] *= a1lo;
            Oa[mt][1][0] *= a0hi; Oa[mt][1][1] *= a1hi;
            Oa[mt][1][2] *= a0hi; Oa[mt][1][3] *= a1hi;
        }

        #pragma unroll
        for (int jc = 0; jc < 8; jc++) {
            float p0a = __shfl_sync(0xffffffffu, P[jc][0], ls0);
            float p0b = __shfl_sync(0xffffffffu, P[jc][1], ls0);
            float p1a = __shfl_sync(0xffffffffu, P[jc][0], ls0 + 2);
            float p1b = __shfl_sync(0xffffffffu, P[jc][1], ls0 + 2);
            uint32_t bn0_0 = __float_as_uint(e ? p0b : p0a);
            uint32_t bn0_1 = __float_as_uint(e ? p1b : p1a);
            float p2a = __shfl_sync(0xffffffffu, P[jc][2], ls0);
            float p2b = __shfl_sync(0xffffffffu, P[jc][3], ls0);
            float p3a = __shfl_sync(0xffffffffu, P[jc][2], ls0 + 2);
            float p3b = __shfl_sync(0xffffffffu, P[jc][3], ls0 + 2);
            uint32_t bn1_0 = __float_as_uint(e ? p2b : p2a);
            uint32_t bn1_1 = __float_as_uint(e ? p3b : p3a);
            #pragma unroll
            for (int mt = 0; mt < 4; mt++) {
                const float* vr = &vs[(16*mt + r)*68 + 8*jc + q4];
                uint32_t a0 = __float_as_uint(vr[0]);
                uint32_t a1 = __float_as_uint(vr[8*68]);
                uint32_t a2 = __float_as_uint(vr[4]);
                uint32_t a3 = __float_as_uint(vr[8*68 + 4]);
                mma_tf32(Oa[mt][0][0], Oa[mt][0][1], Oa[mt][0][2], Oa[mt][0][3],
                         a0, a1, a2, a3, bn0_0, bn0_1);
                mma_tf32(Oa[mt][1][0], Oa[mt][1][1], Oa[mt][1][2], Oa[mt][1][3],
                         a0, a1, a2, a3, bn1_0, bn1_1);
            }
        }
    }

    {
        float il_lo = 1.f / l_lo, il_hi = 1.f / l_hi;
        float i0lo = __shfl_sync(0xffffffffu, il_lo, 8*q4);
        float i1lo = __shfl_sync(0xffffffffu, il_lo, 8*q4 + 4);
        float i0hi = __shfl_sync(0xffffffffu, il_hi, 8*q4);
        float i1hi = __shfl_sync(0xffffffffu, il_hi, 8*q4 + 4);
        #pragma unroll
        for (int mt = 0; mt < 4; mt++) {
            Oa[mt][0][0] *= i0lo; Oa[mt][0][1] *= i1lo;
            Oa[mt][0][2] *= i0lo; Oa[mt][0][3] *= i1lo;
            Oa[mt][1][0] *= i0hi; Oa[mt][1][1] *= i1hi;
            Oa[mt][1][2] *= i0hi; Oa[mt][1][3] *= i1hi;
        }
    }
    __syncthreads();
    #pragma unroll
    for (int mt = 0; mt < 4; mt++) {
        int crow = 16*mt + r;
        int ib = 16*w + 2*q4;
        vs[ crow   *68 + ib    ] = Oa[mt][0][0];
        vs[ crow   *68 + ib + 1] = Oa[mt][0][1];
        vs[(crow+8)*68 + ib    ] = Oa[mt][0][2];
        vs[(crow+8)*68 + ib + 1] = Oa[mt][0][3];
        vs[ crow   *68 + ib + 8] = Oa[mt][1][0];
        vs[ crow   *68 + ib + 9] = Oa[mt][1][1];
        vs[(crow+8)*68 + ib + 8] = Oa[mt][1][2];
        vs[(crow+8)*68 + ib + 9] = Oa[mt][1][3];
    }
    __syncthreads();

    const float gam = gamma_p[0];
    const int h = blockIdx.x;
    float sy = (h + 0.5f)*0.15625f - 0.5f;
    int   y0 = (int)floorf(sy);
    float fy = sy - (float)y0;
    int   y0c = max(y0, 0), y1c = min(y0 + 1, 9);

    #pragma unroll
    for (int kk = 0; kk < 8; kk++) {
        int idx4 = t + 128*kk;
        int c = idx4 >> 4, k4 = (idx4 & 15)*4;
        const float* yr0 = g_y4 + ((size_t)b*CCH + c)*100 + y0c*10;
        const float* yr1 = g_y4 + ((size_t)b*CCH + c)*100 + y1c*10;
        size_t off = ((size_t)b*CCH + c)*NN + i0 + k4;
        float4 xv = *(const float4*)(x + off);
        float4 g4 = *(const float4*)(x + (size_t)b*CCH*NN + i0 + k4);
        float xa[4] = {xv.x, xv.y, xv.z, xv.w};
        float ga[4] = {g4.x, g4.y, g4.z, g4.w};
        float res[4];
        #pragma unroll
        for (int u = 0; u < 4; u++) {
            int wpix = k4 + u;
            float sx = (wpix + 0.5f)*0.15625f - 0.5f;
            int   x0i = (int)floorf(sx);
            float fx = sx - (float)x0i;
            int   x0c = max(x0i, 0), x1c = min(x0i + 1, 9);
            float v00 = yr0[x0c], v01 = yr0[x1c];
            float v10 = yr1[x0c], v11 = yr1[x1c];
            float wv = (1.f-fy)*((1.f-fx)*v00 + fx*v01)
                     +       fy*((1.f-fx)*v10 + fx*v11);
            float gate = 1.f/(1.f + __expf(-ga[u]));
            res[u] = gam*vs[c*68 + k4 + u] + xa[u]*(2.f + wv*gate);
        }
        *(float4*)(out + off) = make_float4(res[0], res[1], res[2], res[3]);
    }
}

// ---------------- launch -------------------------------------------------------
extern "C" void kernel_launch(void* const* d_in, const int* in_sizes, int n_in,
                              void* d_out, int out_size)
{
    const float* x     = (const float*)d_in[0];
    const float* qw    = (const float*)d_in[1];
    const float* qb    = (const float*)d_in[2];
    const float* kw    = (const float*)d_in[3];
    const float* kb    = (const float*)d_in[4];
    const float* vw    = (const float*)d_in[5];
    const float* vb    = (const float*)d_in[6];
    const float* gamma = (const float*)d_in[7];
    const float* w1    = (const float*)d_in[8];
    const float* b1    = (const float*)d_in[9];
    const float* w2    = (const float*)d_in[10];
    const float* b2    = (const float*)d_in[11];
    const float* w3    = (const float*)d_in[12];
    const float* b3    = (const float*)d_in[13];
    float* out = (float*)d_out;

    qkv_kernel<<<dim3(64, BATCH), 256>>>(x, qw, qb, kw, kb, vw, vb, w1, b1);
    softpool_kernel<<<100, 256>>>();
    conv23_kernel<<<BATCH, 256>>>(w2, b2, w3, b3);
    flash_tc_kernel<<<dim3(64, BATCH), 128>>>(x, gamma, out);
}

// round 5
// speedup vs baseline: 1.8306x; 1.2321x over previous
#include <cuda_runtime.h>
#include <math.h>
#include <stdint.h>

#define BATCH 4
#define CCH   64
#define NN    4096
#define DQK   8
#define FCH   16

// ---------------- scratch ------------------------------------------------------
__device__ float g_q [BATCH*DQK*NN];   // tf32 bits
__device__ float g_k [BATCH*DQK*NN];   // tf32 bits
__device__ float g_v [BATCH*CCH*NN];   // tf32 bits
__device__ float g_e [BATCH*FCH*NN];   // exp(y1)
__device__ float g_ev[BATCH*FCH*NN];   // exp(y1)*y1
__device__ float g_y2[BATCH*FCH*400];  // softpool out (20x20)
__device__ float g_y4[BATCH*CCH*100];  // sigmoid weights (10x10)

__device__ __forceinline__ float to_tf32(float x){
    uint32_t r;
    asm("cvt.rna.tf32.f32 %0, %1;" : "=r"(r) : "f"(x));
    return __uint_as_float(r);
}
__device__ __forceinline__ void mma_tf32(
    float& d0, float& d1, float& d2, float& d3,
    uint32_t a0, uint32_t a1, uint32_t a2, uint32_t a3,
    uint32_t b0, uint32_t b1)
{
    asm volatile(
        "mma.sync.aligned.m16n8k8.row.col.f32.tf32.tf32.f32 "
        "{%0,%1,%2,%3},{%4,%5,%6,%7},{%8,%9},{%0,%1,%2,%3};"
        : "+f"(d0), "+f"(d1), "+f"(d2), "+f"(d3)
        : "r"(a0), "r"(a1), "r"(a2), "r"(a3), "r"(b0), "r"(b1));
}

// ---------------- kernel 1: fused 1x1 convs, register-blocked ------------------
// thread = (ocg = t>>4 in [0,16), ng = t&15). Each thread: 6 oc x 4 n.
__global__ __launch_bounds__(256) void qkv_kernel(
    const float* __restrict__ x,
    const float* __restrict__ qw, const float* __restrict__ qb,
    const float* __restrict__ kw, const float* __restrict__ kb,
    const float* __restrict__ vw, const float* __restrict__ vb,
    const float* __restrict__ w1, const float* __restrict__ b1)
{
    __shared__ float Ws[96*65];     // pitch 65: oc-stride not bank-aligned
    __shared__ float bs[96];
    __shared__ float xs[64*64];

    const int b  = blockIdx.y;
    const int n0 = blockIdx.x * 64;
    const int t  = threadIdx.x;

    for (int i = t; i < 512;  i += 256) Ws[( 0 + (i>>6))*65 + (i&63)] = qw[i];
    for (int i = t; i < 512;  i += 256) Ws[( 8 + (i>>6))*65 + (i&63)] = kw[i];
    for (int i = t; i < 4096; i += 256) Ws[(16 + (i>>6))*65 + (i&63)] = vw[i];
    for (int i = t; i < 1024; i += 256) Ws[(80 + (i>>6))*65 + (i&63)] = w1[i];
    if (t < 96) {
        float bv;
        if      (t < 8)  bv = qb[t];
        else if (t < 16) bv = kb[t-8];
        else if (t < 80) bv = vb[t-16];
        else             bv = b1[t-80];
        bs[t] = bv;
    }
    #pragma unroll
    for (int kk = 0; kk < 4; kk++) {
        int idx4 = t + 256*kk;
        int c = idx4 >> 4, n4 = idx4 & 15;
        float4 v = *((const float4*)(x + ((size_t)b*CCH + c)*NN + n0) + n4);
        *((float4*)(xs + c*64) + n4) = v;
    }
    __syncthreads();

    const int ng  = t & 15;
    const int ocg = t >> 4;
    float acc[6][4];
    #pragma unroll
    for (int k = 0; k < 6; k++) {
        float bv = bs[ocg*6 + k];
        acc[k][0] = bv; acc[k][1] = bv; acc[k][2] = bv; acc[k][3] = bv;
    }
    #pragma unroll 4
    for (int c = 0; c < 64; c++) {
        float4 xv = *(const float4*)(xs + c*64 + ng*4);
        #pragma unroll
        for (int k = 0; k < 6; k++) {
            float wv = Ws[(ocg*6 + k)*65 + c];
            acc[k][0] += wv*xv.x; acc[k][1] += wv*xv.y;
            acc[k][2] += wv*xv.z; acc[k][3] += wv*xv.w;
        }
    }
    const int gn = n0 + ng*4;
    #pragma unroll
    for (int k = 0; k < 6; k++) {
        int oc = ocg*6 + k;
        if (oc < 80) {
            float4 o = make_float4(to_tf32(acc[k][0]), to_tf32(acc[k][1]),
                                   to_tf32(acc[k][2]), to_tf32(acc[k][3]));
            float* dst;
            if      (oc < 8)  dst = g_q + ((size_t)b*DQK + oc     )*NN + gn;
            else if (oc < 16) dst = g_k + ((size_t)b*DQK + oc - 8 )*NN + gn;
            else              dst = g_v + ((size_t)b*CCH + oc - 16)*NN + gn;
            *(float4*)dst = o;
        } else {
            size_t o = ((size_t)b*FCH + oc - 80)*NN + gn;
            float4 ee, ev;
            float e0 = __expf(acc[k][0]), e1 = __expf(acc[k][1]);
            float e2 = __expf(acc[k][2]), e3 = __expf(acc[k][3]);
            ee = make_float4(e0, e1, e2, e3);
            ev = make_float4(e0*acc[k][0], e1*acc[k][1], e2*acc[k][2], e3*acc[k][3]);
            *(float4*)(g_e  + o) = ee;
            *(float4*)(g_ev + o) = ev;
        }
    }
}

// ---------------- kernel 2: softpool = sum49(ev)/sum49(e) ----------------------
__global__ void softpool_kernel()
{
    int idx = blockIdx.x*blockDim.x + threadIdx.x;     // 25600
    if (idx >= BATCH*FCH*400) return;
    int ox = idx % 20, oy = (idx/20) % 20;
    int c  = (idx/400) % FCH, b = idx/(400*FCH);
    size_t base = ((size_t)b*FCH + c)*NN + (oy*3)*64 + ox*3;
    const float* se  = g_e  + base;
    const float* sev = g_ev + base;
    float num = 0.f, den = 0.f;
    #pragma unroll
    for (int ky = 0; ky < 7; ky++)
        #pragma unroll
        for (int kx = 0; kx < 7; kx++) {
            num += sev[ky*64 + kx];
            den += se [ky*64 + kx];
        }
    g_y2[idx] = num/den;
}

// ---------------- kernel 3: conv2 (3x3 s2 p1) -> conv3 (3x3 p1) + sigmoid ------
__global__ __launch_bounds__(256) void conv23_kernel(
    const float* __restrict__ w2, const float* __restrict__ b2,
    const float* __restrict__ w3, const float* __restrict__ b3)
{
    __shared__ float y2s[FCH*400];
    __shared__ float y3s[FCH*100];
    const int b = blockIdx.x;
    const int t = threadIdx.x;

    for (int o = t; o < FCH*400; o += 256) y2s[o] = g_y2[(size_t)b*FCH*400 + o];
    __syncthreads();

    for (int o = t; o < FCH*100; o += 256) {
        int ox = o % 10, oy = (o/10) % 10, oc = o/100;
        float acc = b2[oc];
        for (int ic = 0; ic < FCH; ic++) {
            const float* src = y2s + ic*400;
            const float* wr  = w2 + (oc*FCH + ic)*9;
            #pragma unroll
            for (int ky = 0; ky < 3; ky++) {
                int iy = oy*2 - 1 + ky;
                if (iy < 0 || iy >= 20) continue;
                #pragma unroll
                for (int kx = 0; kx < 3; kx++) {
                    int ix = ox*2 - 1 + kx;
                    if (ix < 0 || ix >= 20) continue;
                    acc += wr[ky*3+kx] * src[iy*20 + ix];
                }
            }
        }
        y3s[o] = acc;
    }
    __syncthreads();

    for (int o = t; o < CCH*100; o += 256) {
        int ox = o % 10, oy = (o/10) % 10, oc = o/100;
        float acc = b3[oc];
        for (int ic = 0; ic < FCH; ic++) {
            const float* src = y3s + ic*100;
            const float* wr  = w3 + (oc*FCH + ic)*9;
            #pragma unroll
            for (int ky = 0; ky < 3; ky++) {
                int iy = oy - 1 + ky;
                if (iy < 0 || iy >= 10) continue;
                #pragma unroll
                for (int kx = 0; kx < 3; kx++) {
                    int ix = ox - 1 + kx;
                    if (ix < 0 || ix >= 10) continue;
                    acc += wr[ky*3+kx] * src[iy*10 + ix];
                }
            }
        }
        g_y4[(size_t)b*CCH*100 + o] = 1.f/(1.f + __expf(-acc));
    }
}

// ---------------- kernel 4: split-j tensor-core flash + combine + epilogue -----
// 256 threads = 2 groups of 4 warps. Group g handles j in [2048g, 2048g+2048).
// Exact merge of the two partial softmaxes at the end.
__global__ __launch_bounds__(256, 2) void flash_tc_kernel(
    const float* __restrict__ x, const float* __restrict__ gamma_p,
    float* __restrict__ out)
{
    __shared__ float qs[8*72];
    __shared__ float ks[2][8*72];
    __shared__ float vs[2][64*68];   // per-group V; later: [1]=O1 stage, [0]=final O
    __shared__ float ml_m[2][64];
    __shared__ float ml_l[2][64];

    const int b  = blockIdx.y;
    const int i0 = blockIdx.x * 64;
    const int t  = threadIdx.x;
    const int wg = t >> 7;          // j-group 0/1
    const int tg = t & 127;
    const int w4 = tg >> 5;         // warp-in-group: queries [16*w4, 16*w4+16)
    const int lane = t & 31;
    const int r  = lane >> 2;
    const int q4 = lane & 3;

    for (int kx = t; kx < 512; kx += 256) {
        int d = kx >> 6, i = kx & 63;
        qs[d*72 + i] = g_q[((size_t)b*DQK + d)*NN + i0 + i];
    }
    __syncthreads();

    const uint32_t aq0 = __float_as_uint(qs[ q4   *72 + 16*w4 + r    ]);
    const uint32_t aq1 = __float_as_uint(qs[ q4   *72 + 16*w4 + r + 8]);
    const uint32_t aq2 = __float_as_uint(qs[(q4+4)*72 + 16*w4 + r    ]);
    const uint32_t aq3 = __float_as_uint(qs[(q4+4)*72 + 16*w4 + r + 8]);

    float Oa[4][2][4];
    #pragma unroll
    for (int mt = 0; mt < 4; mt++)
        #pragma unroll
        for (int nt = 0; nt < 2; nt++)
            #pragma unroll
            for (int u = 0; u < 4; u++) Oa[mt][nt][u] = 0.f;

    float m_lo = -1e30f, m_hi = -1e30f, l_lo = 0.f, l_hi = 0.f;
    const int ls0 = (lane & 28) | (q4 >> 1);
    const int e   = lane & 1;
    const int bar = wg + 1;

    for (int jt = wg*2048; jt < wg*2048 + 2048; jt += 64) {
        asm volatile("bar.sync %0, 128;" :: "r"(bar));
        for (int kx = tg; kx < 512; kx += 128) {
            int d = kx >> 6, j = kx & 63;
            ks[wg][d*72 + j] = g_k[((size_t)b*DQK + d)*NN + jt + j];
        }
        #pragma unroll
        for (int kk = 0; kk < 8; kk++) {
            int idx4 = tg + 128*kk;
            int c = idx4 >> 4, j4 = idx4 & 15;
            float4 vv = *(const float4*)(g_v + ((size_t)b*CCH + c)*NN + jt + j4*4);
            *(float4*)&vs[wg][c*68 + j4*4] = vv;
        }
        asm volatile("bar.sync %0, 128;" :: "r"(bar));

        float P[8][4];
        #pragma unroll
        for (int t8 = 0; t8 < 8; t8++) {
            uint32_t kb0 = __float_as_uint(ks[wg][ q4   *72 + t8*8 + r]);
            uint32_t kb1 = __float_as_uint(ks[wg][(q4+4)*72 + t8*8 + r]);
            P[t8][0] = P[t8][1] = P[t8][2] = P[t8][3] = 0.f;
            mma_tf32(P[t8][0], P[t8][1], P[t8][2], P[t8][3],
                     aq0, aq1, aq2, aq3, kb0, kb1);
        }

        float mx_lo = -1e30f, mx_hi = -1e30f;
        #pragma unroll
        for (int t8 = 0; t8 < 8; t8++) {
            mx_lo = fmaxf(mx_lo, fmaxf(P[t8][0], P[t8][1]));
            mx_hi = fmaxf(mx_hi, fmaxf(P[t8][2], P[t8][3]));
        }
        mx_lo = fmaxf(mx_lo, __shfl_xor_sync(0xffffffffu, mx_lo, 1));
        mx_lo = fmaxf(mx_lo, __shfl_xor_sync(0xffffffffu, mx_lo, 2));
        mx_hi = fmaxf(mx_hi, __shfl_xor_sync(0xffffffffu, mx_hi, 1));
        mx_hi = fmaxf(mx_hi, __shfl_xor_sync(0xffffffffu, mx_hi, 2));
        float mn_lo = fmaxf(m_lo, mx_lo), mn_hi = fmaxf(m_hi, mx_hi);
        float al_lo = __expf(m_lo - mn_lo), al_hi = __expf(m_hi - mn_hi);
        m_lo = mn_lo; m_hi = mn_hi;
        float s_lo = 0.f, s_hi = 0.f;
        #pragma unroll
        for (int t8 = 0; t8 < 8; t8++) {
            P[t8][0] = __expf(P[t8][0] - m_lo); s_lo += P[t8][0];
            P[t8][1] = __expf(P[t8][1] - m_lo); s_lo += P[t8][1];
            P[t8][2] = __expf(P[t8][2] - m_hi); s_hi += P[t8][2];
            P[t8][3] = __expf(P[t8][3] - m_hi); s_hi += P[t8][3];
        }
        s_lo += __shfl_xor_sync(0xffffffffu, s_lo, 1);
        s_lo += __shfl_xor_sync(0xffffffffu, s_lo, 2);
        s_hi += __shfl_xor_sync(0xffffffffu, s_hi, 1);
        s_hi += __shfl_xor_sync(0xffffffffu, s_hi, 2);
        l_lo = l_lo*al_lo + s_lo;
        l_hi = l_hi*al_hi + s_hi;

        float a0lo = __shfl_sync(0xffffffffu, al_lo, 8*q4);
        float a1lo = __shfl_sync(0xffffffffu, al_lo, 8*q4 + 4);
        float a0hi = __shfl_sync(0xffffffffu, al_hi, 8*q4);
        float a1hi = __shfl_sync(0xffffffffu, al_hi, 8*q4 + 4);
        #pragma unroll
        for (int mt = 0; mt < 4; mt++) {
            Oa[mt][0][0] *= a0lo; Oa[mt][0][1] *= a1lo;
            Oa[mt][0][2] *= a0lo; Oa[mt][0][3] *= a1lo;
            Oa[mt][1][0] *= a0hi; Oa[mt][1][1] *= a1hi;
            Oa[mt][1][2] *= a0hi; Oa[mt][1][3] *= a1hi;
        }

        #pragma unroll
        for (int jc = 0; jc < 8; jc++) {
            float p0a = __shfl_sync(0xffffffffu, P[jc][0], ls0);
            float p0b = __shfl_sync(0xffffffffu, P[jc][1], ls0);
            float p1a = __shfl_sync(0xffffffffu, P[jc][0], ls0 + 2);
            float p1b = __shfl_sync(0xffffffffu, P[jc][1], ls0 + 2);
            uint32_t bn0_0 = __float_as_uint(e ? p0b : p0a);
            uint32_t bn0_1 = __float_as_uint(e ? p1b : p1a);
            float p2a = __shfl_sync(0xffffffffu, P[jc][2], ls0);
            float p2b = __shfl_sync(0xffffffffu, P[jc][3], ls0);
            float p3a = __shfl_sync(0xffffffffu, P[jc][2], ls0 + 2);
            float p3b = __shfl_sync(0xffffffffu, P[jc][3], ls0 + 2);
            uint32_t bn1_0 = __float_as_uint(e ? p2b : p2a);
            uint32_t bn1_1 = __float_as_uint(e ? p3b : p3a);
            #pragma unroll
            for (int mt = 0; mt < 4; mt++) {
                const float* vr = &vs[wg][(16*mt + r)*68 + 8*jc + q4];
                uint32_t a0 = __float_as_uint(vr[0]);
                uint32_t a1 = __float_as_uint(vr[8*68]);
                uint32_t a2 = __float_as_uint(vr[4]);
                uint32_t a3 = __float_as_uint(vr[8*68 + 4]);
                mma_tf32(Oa[mt][0][0], Oa[mt][0][1], Oa[mt][0][2], Oa[mt][0][3],
                         a0, a1, a2, a3, bn0_0, bn0_1);
                mma_tf32(Oa[mt][1][0], Oa[mt][1][1], Oa[mt][1][2], Oa[mt][1][3],
                         a0, a1, a2, a3, bn1_0, bn1_1);
            }
        }
    }

    // ---- stage per-group m/l; group 1 stages raw O^T -----------------------
    __syncthreads();
    if (q4 == 0) {
        ml_m[wg][16*w4 + r    ] = m_lo;  ml_l[wg][16*w4 + r    ] = l_lo;
        ml_m[wg][16*w4 + r + 8] = m_hi;  ml_l[wg][16*w4 + r + 8] = l_hi;
    }
    if (wg == 1) {
        #pragma unroll
        for (int mt = 0; mt < 4; mt++)
            #pragma unroll
            for (int nt = 0; nt < 2; nt++)
                #pragma unroll
                for (int u = 0; u < 4; u++) {
                    int crow = 16*mt + r + 8*(u >> 1);
                    int col  = 16*w4 + 2*q4 + (u & 1) + 8*nt;
                    vs[1][crow*68 + col] = Oa[mt][nt][u];
                }
    }
    __syncthreads();

    // ---- group 0 merges: O = (O0*e^{m0-M} + O1*e^{m1-M}) / L ----------------
    if (wg == 0) {
        float s0[2][2], s1[2][2];
        #pragma unroll
        for (int nt = 0; nt < 2; nt++)
            #pragma unroll
            for (int ee = 0; ee < 2; ee++) {
                int iq = 16*w4 + 2*q4 + ee + 8*nt;
                float m0 = ml_m[0][iq], m1 = ml_m[1][iq];
                float M  = fmaxf(m0, m1);
                float f0 = __expf(m0 - M), f1 = __expf(m1 - M);
                float L  = ml_l[0][iq]*f0 + ml_l[1][iq]*f1;
                s0[nt][ee] = f0 / L;
                s1[nt][ee] = f1 / L;
            }
        #pragma unroll
        for (int mt = 0; mt < 4; mt++)
            #pragma unroll
            for (int nt = 0; nt < 2; nt++)
                #pragma unroll
                for (int u = 0; u < 4; u++) {
                    int ee = u & 1;
                    int crow = 16*mt + r + 8*(u >> 1);
                    int col  = 16*w4 + 2*q4 + ee + 8*nt;
                    float o1 = vs[1][crow*68 + col];
                    vs[0][crow*68 + col] =
                        Oa[mt][nt][u]*s0[nt][ee] + o1*s1[nt][ee];
                }
    }
    __syncthreads();

    // ---- epilogue: out = gamma*O + x*(2 + bilinear(y4)*sigmoid(x_ch0)) ------
    const float gam = gamma_p[0];
    const int h = blockIdx.x;
    float sy = (h + 0.5f)*0.15625f - 0.5f;
    int   y0 = (int)floorf(sy);
    float fy = sy - (float)y0;
    int   y0c = max(y0, 0), y1c = min(y0 + 1, 9);

    #pragma unroll
    for (int kk = 0; kk < 4; kk++) {
        int idx4 = t + 256*kk;
        int c = idx4 >> 4, k4 = (idx4 & 15)*4;
        const float* yr0 = g_y4 + ((size_t)b*CCH + c)*100 + y0c*10;
        const float* yr1 = g_y4 + ((size_t)b*CCH + c)*100 + y1c*10;
        size_t off = ((size_t)b*CCH + c)*NN + i0 + k4;
        float4 xv = *(const float4*)(x + off);
        float4 g4 = *(const float4*)(x + (size_t)b*CCH*NN + i0 + k4);
        float xa[4] = {xv.x, xv.y, xv.z, xv.w};
        float ga[4] = {g4.x, g4.y, g4.z, g4.w};
        float res[4];
        #pragma unroll
        for (int u = 0; u < 4; u++) {
            int wpix = k4 + u;
            float sx = (wpix + 0.5f)*0.15625f - 0.5f;
            int   x0i = (int)floorf(sx);
            float fx = sx - (float)x0i;
            int   x0c = max(x0i, 0), x1c = min(x0i + 1, 9);
            float v00 = yr0[x0c], v01 = yr0[x1c];
            float v10 = yr1[x0c], v11 = yr1[x1c];
            float wv = (1.f-fy)*((1.f-fx)*v00 + fx*v01)
                     +       fy*((1.f-fx)*v10 + fx*v11);
            float gate = 1.f/(1.f + __expf(-ga[u]));
            res[u] = gam*vs[0][c*68 + k4 + u] + xa[u]*(2.f + wv*gate);
        }
        *(float4*)(out + off) = make_float4(res[0], res[1], res[2], res[3]);
    }
}

// ---------------- launch -------------------------------------------------------
extern "C" void kernel_launch(void* const* d_in, const int* in_sizes, int n_in,
                              void* d_out, int out_size)
{
    const float* x     = (const float*)d_in[0];
    const float* qw    = (const float*)d_in[1];
    const float* qb    = (const float*)d_in[2];
    const float* kw    = (const float*)d_in[3];
    const float* kb    = (const float*)d_in[4];
    const float* vw    = (const float*)d_in[5];
    const float* vb    = (const float*)d_in[6];
    const float* gamma = (const float*)d_in[7];
    const float* w1    = (const float*)d_in[8];
    const float* b1    = (const float*)d_in[9];
    const float* w2    = (const float*)d_in[10];
    const float* b2    = (const float*)d_in[11];
    const float* w3    = (const float*)d_in[12];
    const float* b3    = (const float*)d_in[13];
    float* out = (float*)d_out;

    qkv_kernel<<<dim3(64, BATCH), 256>>>(x, qw, qb, kw, kb, vw, vb, w1, b1);
    softpool_kernel<<<100, 256>>>();
    conv23_kernel<<<BATCH, 256>>>(w2, b2, w3, b3);
    flash_tc_kernel<<<dim3(64, BATCH), 256>>>(x, gamma, out);
}

// round 6
// speedup vs baseline: 2.0722x; 1.1320x over previous
#include <cuda_runtime.h>
#include <math.h>
#include <stdint.h>

#define BATCH 4
#define CCH   64
#define NN    4096
#define DQK   8
#define FCH   16

// ---------------- scratch ------------------------------------------------------
__device__ float g_q [BATCH*DQK*NN];   // tf32 bits
__device__ float g_k [BATCH*DQK*NN];   // tf32 bits
__device__ float g_v [BATCH*CCH*NN];   // tf32 bits
__device__ float g_e [BATCH*FCH*NN];   // exp(y1)
__device__ float g_ev[BATCH*FCH*NN];   // exp(y1)*y1
__device__ float g_y2[BATCH*FCH*400];  // softpool out (20x20)
__device__ float g_y4[BATCH*CCH*100];  // sigmoid weights (10x10)

__device__ __forceinline__ float to_tf32(float x){
    uint32_t r;
    asm("cvt.rna.tf32.f32 %0, %1;" : "=r"(r) : "f"(x));
    return __uint_as_float(r);
}
__device__ __forceinline__ void mma_tf32(
    float& d0, float& d1, float& d2, float& d3,
    uint32_t a0, uint32_t a1, uint32_t a2, uint32_t a3,
    uint32_t b0, uint32_t b1)
{
    asm volatile(
        "mma.sync.aligned.m16n8k8.row.col.f32.tf32.tf32.f32 "
        "{%0,%1,%2,%3},{%4,%5,%6,%7},{%8,%9},{%0,%1,%2,%3};"
        : "+f"(d0), "+f"(d1), "+f"(d2), "+f"(d3)
        : "r"(a0), "r"(a1), "r"(a2), "r"(a3), "r"(b0), "r"(b1));
}
__device__ __forceinline__ void cpa16(uint32_t dst, const float* src){
    asm volatile("cp.async.cg.shared.global [%0], [%1], 16;"
                 :: "r"(dst), "l"(src));
}

// flash smem layout (floats)
#define OFF_QS   0                   // 8*72 = 576
#define OFF_KS   576                 // [wg][par] 8*72 each -> 4*576
#define OFF_VS   2880                // [wg][par] 64*68 each -> 4*4352
#define OFF_L    20288               // [2][64]
#define SM_FLTS  20416
#define OFF_OFIN OFF_VS              // final O: reuse vs[0][0]
#define OFF_OST  (OFF_VS + 4352)     // group1 stage: reuse vs[0][1]

// ---------------- kernel 1: fused 1x1 convs, register-blocked ------------------
__global__ __launch_bounds__(256) void qkv_kernel(
    const float* __restrict__ x,
    const float* __restrict__ qw, const float* __restrict__ qb,
    const float* __restrict__ kw, const float* __restrict__ kb,
    const float* __restrict__ vw, const float* __restrict__ vb,
    const float* __restrict__ w1, const float* __restrict__ b1)
{
    __shared__ float Ws[96*65];
    __shared__ float bs[96];
    __shared__ float xs[64*64];

    const int b  = blockIdx.y;
    const int n0 = blockIdx.x * 64;
    const int t  = threadIdx.x;

    for (int i = t; i < 512;  i += 256) Ws[( 0 + (i>>6))*65 + (i&63)] = qw[i];
    for (int i = t; i < 512;  i += 256) Ws[( 8 + (i>>6))*65 + (i&63)] = kw[i];
    for (int i = t; i < 4096; i += 256) Ws[(16 + (i>>6))*65 + (i&63)] = vw[i];
    for (int i = t; i < 1024; i += 256) Ws[(80 + (i>>6))*65 + (i&63)] = w1[i];
    if (t < 96) {
        float bv;
        if      (t < 8)  bv = qb[t];
        else if (t < 16) bv = kb[t-8];
        else if (t < 80) bv = vb[t-16];
        else             bv = b1[t-80];
        bs[t] = bv;
    }
    #pragma unroll
    for (int kk = 0; kk < 4; kk++) {
        int idx4 = t + 256*kk;
        int c = idx4 >> 4, n4 = idx4 & 15;
        float4 v = *((const float4*)(x + ((size_t)b*CCH + c)*NN + n0) + n4);
        *((float4*)(xs + c*64) + n4) = v;
    }
    __syncthreads();

    const int ng  = t & 15;
    const int ocg = t >> 4;
    float acc[6][4];
    #pragma unroll
    for (int k = 0; k < 6; k++) {
        float bv = bs[ocg*6 + k];
        acc[k][0] = bv; acc[k][1] = bv; acc[k][2] = bv; acc[k][3] = bv;
    }
    #pragma unroll 4
    for (int c = 0; c < 64; c++) {
        float4 xv = *(const float4*)(xs + c*64 + ng*4);
        #pragma unroll
        for (int k = 0; k < 6; k++) {
            float wv = Ws[(ocg*6 + k)*65 + c];
            acc[k][0] += wv*xv.x; acc[k][1] += wv*xv.y;
            acc[k][2] += wv*xv.z; acc[k][3] += wv*xv.w;
        }
    }
    const int gn = n0 + ng*4;
    #pragma unroll
    for (int k = 0; k < 6; k++) {
        int oc = ocg*6 + k;
        if (oc < 80) {
            float4 o = make_float4(to_tf32(acc[k][0]), to_tf32(acc[k][1]),
                                   to_tf32(acc[k][2]), to_tf32(acc[k][3]));
            float* dst;
            if      (oc < 8)  dst = g_q + ((size_t)b*DQK + oc     )*NN + gn;
            else if (oc < 16) dst = g_k + ((size_t)b*DQK + oc - 8 )*NN + gn;
            else              dst = g_v + ((size_t)b*CCH + oc - 16)*NN + gn;
            *(float4*)dst = o;
        } else {
            size_t o = ((size_t)b*FCH + oc - 80)*NN + gn;
            float e0 = __expf(acc[k][0]), e1 = __expf(acc[k][1]);
            float e2 = __expf(acc[k][2]), e3 = __expf(acc[k][3]);
            *(float4*)(g_e  + o) = make_float4(e0, e1, e2, e3);
            *(float4*)(g_ev + o) = make_float4(e0*acc[k][0], e1*acc[k][1],
                                               e2*acc[k][2], e3*acc[k][3]);
        }
    }
}

// ---------------- kernel 2: softpool = sum49(ev)/sum49(e) ----------------------
__global__ void softpool_kernel()
{
    int idx = blockIdx.x*blockDim.x + threadIdx.x;
    if (idx >= BATCH*FCH*400) return;
    int ox = idx % 20, oy = (idx/20) % 20;
    int c  = (idx/400) % FCH, b = idx/(400*FCH);
    size_t base = ((size_t)b*FCH + c)*NN + (oy*3)*64 + ox*3;
    const float* se  = g_e  + base;
    const float* sev = g_ev + base;
    float num = 0.f, den = 0.f;
    #pragma unroll
    for (int ky = 0; ky < 7; ky++)
        #pragma unroll
        for (int kx = 0; kx < 7; kx++) {
            num += sev[ky*64 + kx];
            den += se [ky*64 + kx];
        }
    g_y2[idx] = num/den;
}

// ---------------- kernel 3: conv2 -> conv3 + sigmoid ---------------------------
__global__ __launch_bounds__(256) void conv23_kernel(
    const float* __restrict__ w2, const float* __restrict__ b2,
    const float* __restrict__ w3, const float* __restrict__ b3)
{
    __shared__ float y2s[FCH*400];
    __shared__ float y3s[FCH*100];
    const int b = blockIdx.x;
    const int t = threadIdx.x;

    for (int o = t; o < FCH*400; o += 256) y2s[o] = g_y2[(size_t)b*FCH*400 + o];
    __syncthreads();

    for (int o = t; o < FCH*100; o += 256) {
        int ox = o % 10, oy = (o/10) % 10, oc = o/100;
        float acc = b2[oc];
        for (int ic = 0; ic < FCH; ic++) {
            const float* src = y2s + ic*400;
            const float* wr  = w2 + (oc*FCH + ic)*9;
            #pragma unroll
            for (int ky = 0; ky < 3; ky++) {
                int iy = oy*2 - 1 + ky;
                if (iy < 0 || iy >= 20) continue;
                #pragma unroll
                for (int kx = 0; kx < 3; kx++) {
                    int ix = ox*2 - 1 + kx;
                    if (ix < 0 || ix >= 20) continue;
                    acc += wr[ky*3+kx] * src[iy*20 + ix];
                }
            }
        }
        y3s[o] = acc;
    }
    __syncthreads();

    for (int o = t; o < CCH*100; o += 256) {
        int ox = o % 10, oy = (o/10) % 10, oc = o/100;
        float acc = b3[oc];
        for (int ic = 0; ic < FCH; ic++) {
            const float* src = y3s + ic*100;
            const float* wr  = w3 + (oc*FCH + ic)*9;
            #pragma unroll
            for (int ky = 0; ky < 3; ky++) {
                int iy = oy - 1 + ky;
                if (iy < 0 || iy >= 10) continue;
                #pragma unroll
                for (int kx = 0; kx < 3; kx++) {
                    int ix = ox - 1 + kx;
                    if (ix < 0 || ix >= 10) continue;
                    acc += wr[ky*3+kx] * src[iy*10 + ix];
                }
            }
        }
        g_y4[(size_t)b*CCH*100 + o] = 1.f/(1.f + __expf(-acc));
    }
}

// ---------------- kernel 4: flash, fixed-shift softmax + cp.async pipeline -----
// 256 threads = 2 groups of 4 warps; group g: j in [2048g, 2048g+2048), 2-stage
// double-buffered K/V via cp.async. P = exp(s - 12) (shift cancels exactly).
__global__ __launch_bounds__(256, 2) void flash_tc_kernel(
    const float* __restrict__ x, const float* __restrict__ gamma_p,
    float* __restrict__ out)
{
    extern __shared__ __align__(16) float sm[];
    const int b  = blockIdx.y;
    const int i0 = blockIdx.x * 64;
    const int t  = threadIdx.x;
    const int wg = t >> 7;
    const int tg = t & 127;
    const int w4 = tg >> 5;
    const int lane = t & 31;
    const int r  = lane >> 2;
    const int q4 = lane & 3;
    const int bar = wg + 1;

    // load Q
    for (int kx = t; kx < 512; kx += 256) {
        int d = kx >> 6, i = kx & 63;
        sm[OFF_QS + d*72 + i] = g_q[((size_t)b*DQK + d)*NN + i0 + i];
    }

    // cp.async source/dest precompute for this thread
    const int kd = tg >> 4, kj4 = tg & 15;                 // K chunk
    const float* ksrc = g_k + ((size_t)b*DQK + kd)*NN + wg*2048 + kj4*4;
    uint32_t kdst[2];
    const float* vsrc[8];
    uint32_t vdst[2][8];
    #pragma unroll
    for (int p = 0; p < 2; p++)
        kdst[p] = (uint32_t)__cvta_generic_to_shared(
            sm + OFF_KS + (wg*2 + p)*576 + kd*72 + kj4*4);
    #pragma unroll
    for (int kk = 0; kk < 8; kk++) {
        int idx4 = tg + 128*kk;
        int c = idx4 >> 4, j4 = idx4 & 15;
        vsrc[kk] = g_v + ((size_t)b*CCH + c)*NN + wg*2048 + j4*4;
        #pragma unroll
        for (int p = 0; p < 2; p++)
            vdst[p][kk] = (uint32_t)__cvta_generic_to_shared(
                sm + OFF_VS + (wg*2 + p)*4352 + c*68 + j4*4);
    }

    // prologue: issue tile 0 into parity 0
    cpa16(kdst[0], ksrc);
    #pragma unroll
    for (int kk = 0; kk < 8; kk++) cpa16(vdst[0][kk], vsrc[kk]);
    asm volatile("cp.async.commit_group;");

    __syncthreads();
    const uint32_t aq0 = __float_as_uint(sm[OFF_QS +  q4   *72 + 16*w4 + r    ]);
    const uint32_t aq1 = __float_as_uint(sm[OFF_QS +  q4   *72 + 16*w4 + r + 8]);
    const uint32_t aq2 = __float_as_uint(sm[OFF_QS + (q4+4)*72 + 16*w4 + r    ]);
    const uint32_t aq3 = __float_as_uint(sm[OFF_QS + (q4+4)*72 + 16*w4 + r + 8]);

    float Oa[4][2][4];
    #pragma unroll
    for (int mt = 0; mt < 4; mt++)
        #pragma unroll
        for (int nt = 0; nt < 2; nt++)
            #pragma unroll
            for (int u = 0; u < 4; u++) Oa[mt][nt][u] = 0.f;
    float l_lo = 0.f, l_hi = 0.f;

    const int ls0 = (lane & 28) | (q4 >> 1);
    const int e   = lane & 1;
    int par = 0;

    for (int it = 0; it < 32; ++it) {
        asm volatile("bar.sync %0, 128;" :: "r"(bar));   // buf[par^1] free
        if (it + 1 < 32) {                               // prefetch tile it+1
            int off = (it + 1)*64;
            cpa16(kdst[par^1], ksrc + off);
            #pragma unroll
            for (int kk = 0; kk < 8; kk++) cpa16(vdst[par^1][kk], vsrc[kk] + off);
        }
        asm volatile("cp.async.commit_group;");
        asm volatile("cp.async.wait_group 1;");          // tile it landed (mine)
        asm volatile("bar.sync %0, 128;" :: "r"(bar));   // ... and everyone's

        const float* ksb = sm + OFF_KS + (wg*2 + par)*576;
        const float* vsb = sm + OFF_VS + (wg*2 + par)*4352;

        // ---- S = Q*K, P = exp(S - 12)
        float P[8][4];
        #pragma unroll
        for (int t8 = 0; t8 < 8; t8++) {
            uint32_t kb0 = __float_as_uint(ksb[ q4   *72 + t8*8 + r]);
            uint32_t kb1 = __float_as_uint(ksb[(q4+4)*72 + t8*8 + r]);
            P[t8][0] = P[t8][1] = P[t8][2] = P[t8][3] = 0.f;
            mma_tf32(P[t8][0], P[t8][1], P[t8][2], P[t8][3],
                     aq0, aq1, aq2, aq3, kb0, kb1);
        }
        #pragma unroll
        for (int t8 = 0; t8 < 8; t8++) {
            P[t8][0] = __expf(P[t8][0] - 12.f); l_lo += P[t8][0];
            P[t8][1] = __expf(P[t8][1] - 12.f); l_lo += P[t8][1];
            P[t8][2] = __expf(P[t8][2] - 12.f); l_hi += P[t8][2];
            P[t8][3] = __expf(P[t8][3] - 12.f); l_hi += P[t8][3];
        }

        // ---- O^T += V * P^T
        #pragma unroll
        for (int jc = 0; jc < 8; jc++) {
            float p0a = __shfl_sync(0xffffffffu, P[jc][0], ls0);
            float p0b = __shfl_sync(0xffffffffu, P[jc][1], ls0);
            float p1a = __shfl_sync(0xffffffffu, P[jc][0], ls0 + 2);
            float p1b = __shfl_sync(0xffffffffu, P[jc][1], ls0 + 2);
            uint32_t bn0_0 = __float_as_uint(e ? p0b : p0a);
            uint32_t bn0_1 = __float_as_uint(e ? p1b : p1a);
            float p2a = __shfl_sync(0xffffffffu, P[jc][2], ls0);
            float p2b = __shfl_sync(0xffffffffu, P[jc][3], ls0);
            float p3a = __shfl_sync(0xffffffffu, P[jc][2], ls0 + 2);
            float p3b = __shfl_sync(0xffffffffu, P[jc][3], ls0 + 2);
            uint32_t bn1_0 = __float_as_uint(e ? p2b : p2a);
            uint32_t bn1_1 = __float_as_uint(e ? p3b : p3a);
            #pragma unroll
            for (int mt = 0; mt < 4; mt++) {
                const float* vr = &vsb[(16*mt + r)*68 + 8*jc + q4];
                uint32_t a0 = __float_as_uint(vr[0]);
                uint32_t a1 = __float_as_uint(vr[8*68]);
                uint32_t a2 = __float_as_uint(vr[4]);
                uint32_t a3 = __float_as_uint(vr[8*68 + 4]);
                mma_tf32(Oa[mt][0][0], Oa[mt][0][1], Oa[mt][0][2], Oa[mt][0][3],
                         a0, a1, a2, a3, bn0_0, bn0_1);
                mma_tf32(Oa[mt][1][0], Oa[mt][1][1], Oa[mt][1][2], Oa[mt][1][3],
                         a0, a1, a2, a3, bn1_0, bn1_1);
            }
        }
        par ^= 1;
    }

    // ---- reduce l across the quad (cols), stage per-group ---------------------
    l_lo += __shfl_xor_sync(0xffffffffu, l_lo, 1);
    l_lo += __shfl_xor_sync(0xffffffffu, l_lo, 2);
    l_hi += __shfl_xor_sync(0xffffffffu, l_hi, 1);
    l_hi += __shfl_xor_sync(0xffffffffu, l_hi, 2);
    __syncthreads();
    if (q4 == 0) {
        sm[OFF_L + wg*64 + 16*w4 + r    ] = l_lo;
        sm[OFF_L + wg*64 + 16*w4 + r + 8] = l_hi;
    }
    if (wg == 1) {
        #pragma unroll
        for (int mt = 0; mt < 4; mt++)
            #pragma unroll
            for (int nt = 0; nt < 2; nt++)
                #pragma unroll
                for (int u = 0; u < 4; u++) {
                    int crow = 16*mt + r + 8*(u >> 1);
                    int col  = 16*w4 + 2*q4 + (u & 1) + 8*nt;
                    sm[OFF_OST + crow*68 + col] = Oa[mt][nt][u];
                }
    }
    __syncthreads();

    // ---- group 0 merges: O = (O0 + O1) / (l0 + l1) ---------------------------
    if (wg == 0) {
        float inv[2][2];
        #pragma unroll
        for (int nt = 0; nt < 2; nt++)
            #pragma unroll
            for (int ee = 0; ee < 2; ee++) {
                int iq = 16*w4 + 2*q4 + ee + 8*nt;
                inv[nt][ee] = 1.f / (sm[OFF_L + iq] + sm[OFF_L + 64 + iq]);
            }
        #pragma unroll
        for (int mt = 0; mt < 4; mt++)
            #pragma unroll
            for (int nt = 0; nt < 2; nt++)
                #pragma unroll
                for (int u = 0; u < 4; u++) {
                    int ee = u & 1;
                    int crow = 16*mt + r + 8*(u >> 1);
                    int col  = 16*w4 + 2*q4 + ee + 8*nt;
                    sm[OFF_OFIN + crow*68 + col] =
                        (Oa[mt][nt][u] + sm[OFF_OST + crow*68 + col]) * inv[nt][ee];
                }
    }
    __syncthreads();

    // ---- epilogue: out = gamma*O + x*(2 + bilinear(y4)*sigmoid(x_ch0)) --------
    const float gam = gamma_p[0];
    const int h = blockIdx.x;
    float sy = (h + 0.5f)*0.15625f - 0.5f;
    int   y0 = (int)floorf(sy);
    float fy = sy - (float)y0;
    int   y0c = max(y0, 0), y1c = min(y0 + 1, 9);

    #pragma unroll
    for (int kk = 0; kk < 4; kk++) {
        int idx4 = t + 256*kk;
        int c = idx4 >> 4, k4 = (idx4 & 15)*4;
        const float* yr0 = g_y4 + ((size_t)b*CCH + c)*100 + y0c*10;
        const float* yr1 = g_y4 + ((size_t)b*CCH + c)*100 + y1c*10;
        size_t off = ((size_t)b*CCH + c)*NN + i0 + k4;
        float4 xv = *(const float4*)(x + off);
        float4 g4 = *(const float4*)(x + (size_t)b*CCH*NN + i0 + k4);
        float xa[4] = {xv.x, xv.y, xv.z, xv.w};
        float ga[4] = {g4.x, g4.y, g4.z, g4.w};
        float res[4];
        #pragma unroll
        for (int u = 0; u < 4; u++) {
            int wpix = k4 + u;
            float sx = (wpix + 0.5f)*0.15625f - 0.5f;
            int   x0i = (int)floorf(sx);
            float fx = sx - (float)x0i;
            int   x0c = max(x0i, 0), x1c = min(x0i + 1, 9);
            float v00 = yr0[x0c], v01 = yr0[x1c];
            float v10 = yr1[x0c], v11 = yr1[x1c];
            float wv = (1.f-fy)*((1.f-fx)*v00 + fx*v01)
                     +       fy*((1.f-fx)*v10 + fx*v11);
            float gate = 1.f/(1.f + __expf(-ga[u]));
            res[u] = gam*sm[OFF_OFIN + c*68 + k4 + u] + xa[u]*(2.f + wv*gate);
        }
        *(float4*)(out + off) = make_float4(res[0], res[1], res[2], res[3]);
    }
}

// ---------------- launch -------------------------------------------------------
extern "C" void kernel_launch(void* const* d_in, const int* in_sizes, int n_in,
                              void* d_out, int out_size)
{
    const float* x     = (const float*)d_in[0];
    const float* qw    = (const float*)d_in[1];
    const float* qb    = (const float*)d_in[2];
    const float* kw    = (const float*)d_in[3];
    const float* kb    = (const float*)d_in[4];
    const float* vw    = (const float*)d_in[5];
    const float* vb    = (const float*)d_in[6];
    const float* gamma = (const float*)d_in[7];
    const float* w1    = (const float*)d_in[8];
    const float* b1    = (const float*)d_in[9];
    const float* w2    = (const float*)d_in[10];
    const float* b2    = (const float*)d_in[11];
    const float* w3    = (const float*)d_in[12];
    const float* b3    = (const float*)d_in[13];
    float* out = (float*)d_out;

    const int smem = SM_FLTS * 4;   // 81664 B
    cudaFuncSetAttribute(flash_tc_kernel,
                         cudaFuncAttributeMaxDynamicSharedMemorySize, smem);

    qkv_kernel<<<dim3(64, BATCH), 256>>>(x, qw, qb, kw, kb, vw, vb, w1, b1);
    softpool_kernel<<<100, 256>>>();
    conv23_kernel<<<BATCH, 256>>>(w2, b2, w3, b3);
    flash_tc_kernel<<<dim3(64, BATCH), 256, smem>>>(x, gamma, out);
}

// round 8
// speedup vs baseline: 3.3459x; 1.6147x over previous
#include <cuda_runtime.h>
#include <math.h>
#include <stdint.h>

#define BATCH 4
#define CCH   64
#define NN    4096
#define DQK   8
#define FCH   16

// ---------------- scratch ------------------------------------------------------
__device__ float g_q [BATCH*DQK*NN];   // tf32 bits
__device__ float g_k [BATCH*DQK*NN];   // tf32 bits
__device__ float g_v [BATCH*CCH*NN];   // tf32 bits
__device__ float g_e [BATCH*FCH*NN];   // exp(y1)
__device__ float g_ev[BATCH*FCH*NN];   // exp(y1)*y1
__device__ float g_y2[BATCH*FCH*400];  // softpool out (20x20)
__device__ float g_y4[BATCH*CCH*100];  // sigmoid weights (10x10)

__device__ __forceinline__ float to_tf32(float x){
    uint32_t r;
    asm("cvt.rna.tf32.f32 %0, %1;" : "=r"(r) : "f"(x));
    return __uint_as_float(r);
}
__device__ __forceinline__ void mma_tf32(
    float& d0, float& d1, float& d2, float& d3,
    uint32_t a0, uint32_t a1, uint32_t a2, uint32_t a3,
    uint32_t b0, uint32_t b1)
{
    asm volatile(
        "mma.sync.aligned.m16n8k8.row.col.f32.tf32.tf32.f32 "
        "{%0,%1,%2,%3},{%4,%5,%6,%7},{%8,%9},{%0,%1,%2,%3};"
        : "+f"(d0), "+f"(d1), "+f"(d2), "+f"(d3)
        : "r"(a0), "r"(a1), "r"(a2), "r"(a3), "r"(b0), "r"(b1));
}
__device__ __forceinline__ void cpa16(uint32_t dst, const float* src){
    asm volatile("cp.async.cg.shared.global [%0], [%1], 16;"
                 :: "r"(dst), "l"(src));
}
__device__ __forceinline__ void ldsm_x4(uint32_t& a0, uint32_t& a1,
                                        uint32_t& a2, uint32_t& a3, uint32_t addr){
    asm volatile("ldmatrix.sync.aligned.m8n8.x4.shared.b16 {%0,%1,%2,%3}, [%4];"
                 : "=r"(a0), "=r"(a1), "=r"(a2), "=r"(a3) : "r"(addr));
}

// flash smem layout (floats)
#define OFF_QS   0                   // 8*72 = 576
#define OFF_KS   576                 // [wg][par] 8*72 each -> 4*576
#define OFF_VS   2880                // [wg][par] 64*68 each -> 4*4352
#define OFF_L    20288               // [2][64]
#define SM_FLTS  20416
#define OFF_OFIN OFF_VS
#define OFF_OST  (OFF_VS + 4352)

// ---------------- kernel 1: fused 1x1 convs, register-blocked ------------------
__global__ __launch_bounds__(256) void qkv_kernel(
    const float* __restrict__ x,
    const float* __restrict__ qw, const float* __restrict__ qb,
    const float* __restrict__ kw, const float* __restrict__ kb,
    const float* __restrict__ vw, const float* __restrict__ vb,
    const float* __restrict__ w1, const float* __restrict__ b1)
{
    __shared__ float Ws[96*65];
    __shared__ float bs[96];
    __shared__ float xs[64*64];

    const int b  = blockIdx.y;
    const int n0 = blockIdx.x * 64;
    const int t  = threadIdx.x;

    for (int i = t; i < 512;  i += 256) Ws[( 0 + (i>>6))*65 + (i&63)] = qw[i];
    for (int i = t; i < 512;  i += 256) Ws[( 8 + (i>>6))*65 + (i&63)] = kw[i];
    for (int i = t; i < 4096; i += 256) Ws[(16 + (i>>6))*65 + (i&63)] = vw[i];
    for (int i = t; i < 1024; i += 256) Ws[(80 + (i>>6))*65 + (i&63)] = w1[i];
    if (t < 96) {
        float bv;
        if      (t < 8)  bv = qb[t];
        else if (t < 16) bv = kb[t-8];
        else if (t < 80) bv = vb[t-16];
        else             bv = b1[t-80];
        bs[t] = bv;
    }
    #pragma unroll
    for (int kk = 0; kk < 4; kk++) {
        int idx4 = t + 256*kk;
        int c = idx4 >> 4, n4 = idx4 & 15;
        float4 v = *((const float4*)(x + ((size_t)b*CCH + c)*NN + n0) + n4);
        *((float4*)(xs + c*64) + n4) = v;
    }
    __syncthreads();

    const int ng  = t & 15;
    const int ocg = t >> 4;
    float acc[6][4];
    #pragma unroll
    for (int k = 0; k < 6; k++) {
        float bv = bs[ocg*6 + k];
        acc[k][0] = bv; acc[k][1] = bv; acc[k][2] = bv; acc[k][3] = bv;
    }
    #pragma unroll 4
    for (int c = 0; c < 64; c++) {
        float4 xv = *(const float4*)(xs + c*64 + ng*4);
        #pragma unroll
        for (int k = 0; k < 6; k++) {
            float wv = Ws[(ocg*6 + k)*65 + c];
            acc[k][0] += wv*xv.x; acc[k][1] += wv*xv.y;
            acc[k][2] += wv*xv.z; acc[k][3] += wv*xv.w;
        }
    }
    const int gn = n0 + ng*4;
    #pragma unroll
    for (int k = 0; k < 6; k++) {
        int oc = ocg*6 + k;
        if (oc < 80) {
            float4 o = make_float4(to_tf32(acc[k][0]), to_tf32(acc[k][1]),
                                   to_tf32(acc[k][2]), to_tf32(acc[k][3]));
            float* dst;
            if      (oc < 8)  dst = g_q + ((size_t)b*DQK + oc     )*NN + gn;
            else if (oc < 16) dst = g_k + ((size_t)b*DQK + oc - 8 )*NN + gn;
            else              dst = g_v + ((size_t)b*CCH + oc - 16)*NN + gn;
            *(float4*)dst = o;
        } else {
            size_t o = ((size_t)b*FCH + oc - 80)*NN + gn;
            float e0 = __expf(acc[k][0]), e1 = __expf(acc[k][1]);
            float e2 = __expf(acc[k][2]), e3 = __expf(acc[k][3]);
            *(float4*)(g_e  + o) = make_float4(e0, e1, e2, e3);
            *(float4*)(g_ev + o) = make_float4(e0*acc[k][0], e1*acc[k][1],
                                               e2*acc[k][2], e3*acc[k][3]);
        }
    }
}

// ---------------- kernel 2: softpool = sum49(ev)/sum49(e) ----------------------
__global__ void softpool_kernel()
{
    int idx = blockIdx.x*blockDim.x + threadIdx.x;
    if (idx >= BATCH*FCH*400) return;
    int ox = idx % 20, oy = (idx/20) % 20;
    int c  = (idx/400) % FCH, b = idx/(400*FCH);
    size_t base = ((size_t)b*FCH + c)*NN + (oy*3)*64 + ox*3;
    const float* se  = g_e  + base;
    const float* sev = g_ev + base;
    float num = 0.f, den = 0.f;
    #pragma unroll
    for (int ky = 0; ky < 7; ky++)
        #pragma unroll
        for (int kx = 0; kx < 7; kx++) {
            num += sev[ky*64 + kx];
            den += se [ky*64 + kx];
        }
    g_y2[idx] = num/den;
}

// ---------------- kernel 3: conv2 (redundant) -> conv3(4 oc) + sigmoid ---------
// 64 blocks = (b, og). Each block recomputes all of conv2 (cheap), then conv3
// for its own 4 output channels.
__global__ __launch_bounds__(256) void conv23_kernel(
    const float* __restrict__ w2, const float* __restrict__ b2,
    const float* __restrict__ w3, const float* __restrict__ b3)
{
    __shared__ float y2s[FCH*400];
    __shared__ float y3s[FCH*100];
    const int b  = blockIdx.x >> 4;
    const int og = blockIdx.x & 15;
    const int t  = threadIdx.x;

    for (int o = t; o < FCH*400; o += 256) y2s[o] = g_y2[(size_t)b*FCH*400 + o];
    __syncthreads();

    for (int o = t; o < FCH*100; o += 256) {
        int ox = o % 10, oy = (o/10) % 10, oc = o/100;
        float acc = b2[oc];
        for (int ic = 0; ic < FCH; ic++) {
            const float* src = y2s + ic*400;
            const float* wr  = w2 + (oc*FCH + ic)*9;
            #pragma unroll
            for (int ky = 0; ky < 3; ky++) {
                int iy = oy*2 - 1 + ky;
                if (iy < 0 || iy >= 20) continue;
                #pragma unroll
                for (int kx = 0; kx < 3; kx++) {
                    int ix = ox*2 - 1 + kx;
                    if (ix < 0 || ix >= 20) continue;
                    acc += wr[ky*3+kx] * src[iy*20 + ix];
                }
            }
        }
        y3s[o] = acc;
    }
    __syncthreads();

    for (int o = t; o < 400; o += 256) {
        int ox = o % 10, oy = (o/10) % 10;
        int oc = og*4 + o/100;
        float acc = b3[oc];
        for (int ic = 0; ic < FCH; ic++) {
            const float* src = y3s + ic*100;
            const float* wr  = w3 + (oc*FCH + ic)*9;
            #pragma unroll
            for (int ky = 0; ky < 3; ky++) {
                int iy = oy - 1 + ky;
                if (iy < 0 || iy >= 10) continue;
                #pragma unroll
                for (int kx = 0; kx < 3; kx++) {
                    int ix = ox - 1 + kx;
                    if (ix < 0 || ix >= 10) continue;
                    acc += wr[ky*3+kx] * src[iy*10 + ix];
                }
            }
        }
        g_y4[((size_t)b*CCH + oc)*100 + (o % 100)] = 1.f/(1.f + __expf(-acc));
    }
}

// ---------------- kernel 4: flash, fixed shift + cp.async + ldmatrix -----------
__global__ __launch_bounds__(256, 2) void flash_tc_kernel(
    const float* __restrict__ x, const float* __restrict__ gamma_p,
    float* __restrict__ out)
{
    extern __shared__ __align__(16) float sm[];
    const int b  = blockIdx.y;
    const int i0 = blockIdx.x * 64;
    const int t  = threadIdx.x;
    const int wg = t >> 7;
    const int tg = t & 127;
    const int w4 = tg >> 5;
    const int lane = t & 31;
    const int r  = lane >> 2;
    const int q4 = lane & 3;
    const int bar = wg + 1;

    for (int kx = t; kx < 512; kx += 256) {
        int d = kx >> 6, i = kx & 63;
        sm[OFF_QS + d*72 + i] = g_q[((size_t)b*DQK + d)*NN + i0 + i];
    }

    const int kd = tg >> 4, kj4 = tg & 15;
    const float* ksrc = g_k + ((size_t)b*DQK + kd)*NN + wg*2048 + kj4*4;
    uint32_t kdst[2];
    const float* vsrc[8];
    uint32_t vdst[2][8];
    #pragma unroll
    for (int p = 0; p < 2; p++)
        kdst[p] = (uint32_t)__cvta_generic_to_shared(
            sm + OFF_KS + (wg*2 + p)*576 + kd*72 + kj4*4);
    #pragma unroll
    for (int kk = 0; kk < 8; kk++) {
        int idx4 = tg + 128*kk;
        int c = idx4 >> 4, j4 = idx4 & 15;
        vsrc[kk] = g_v + ((size_t)b*CCH + c)*NN + wg*2048 + j4*4;
        #pragma unroll
        for (int p = 0; p < 2; p++)
            vdst[p][kk] = (uint32_t)__cvta_generic_to_shared(
                sm + OFF_VS + (wg*2 + p)*4352 + c*68 + j4*4);
    }

    // ldmatrix lane address offset (bytes): matrices 0..3 <- (rows, rows+8,
    // rows@col+4, rows+8@col+4); lane provides its matrix-row address.
    const uint32_t lm_off = (uint32_t)(((lane & 7) + 8*((lane >> 3) & 1))*272
                                      + (lane >> 4)*16);
    uint32_t vlm[2];
    #pragma unroll
    for (int p = 0; p < 2; p++)
        vlm[p] = (uint32_t)__cvta_generic_to_shared(
                     sm + OFF_VS + (wg*2 + p)*4352) + lm_off;

    cpa16(kdst[0], ksrc);
    #pragma unroll
    for (int kk = 0; kk < 8; kk++) cpa16(vdst[0][kk], vsrc[kk]);
    asm volatile("cp.async.commit_group;");

    __syncthreads();
    const uint32_t aq0 = __float_as_uint(sm[OFF_QS +  q4   *72 + 16*w4 + r    ]);
    const uint32_t aq1 = __float_as_uint(sm[OFF_QS +  q4   *72 + 16*w4 + r + 8]);
    const uint32_t aq2 = __float_as_uint(sm[OFF_QS + (q4+4)*72 + 16*w4 + r    ]);
    const uint32_t aq3 = __float_as_uint(sm[OFF_QS + (q4+4)*72 + 16*w4 + r + 8]);

    float Oa[4][2][4];
    #pragma unroll
    for (int mt = 0; mt < 4; mt++)
        #pragma unroll
        for (int nt = 0; nt < 2; nt++)
            #pragma unroll
            for (int u = 0; u < 4; u++) Oa[mt][nt][u] = 0.f;
    float l_lo = 0.f, l_hi = 0.f;

    const int ls0 = (lane & 28) | (q4 >> 1);
    const int e   = lane & 1;
    int par = 0;

    for (int it = 0; it < 32; ++it) {
        asm volatile("bar.sync %0, 128;" :: "r"(bar));
        if (it + 1 < 32) {
            int off = (it + 1)*64;
            cpa16(kdst[par^1], ksrc + off);
            #pragma unroll
            for (int kk = 0; kk < 8; kk++) cpa16(vdst[par^1][kk], vsrc[kk] + off);
        }
        asm volatile("cp.async.commit_group;");
        asm volatile("cp.async.wait_group 1;");
        asm volatile("bar.sync %0, 128;" :: "r"(bar));

        const float* ksb = sm + OFF_KS + (wg*2 + par)*576;
        const uint32_t vbase = vlm[par];

        // ---- S = Q*K, P = exp(S - 12)
        float P[8][4];
        #pragma unroll
        for (int t8 = 0; t8 < 8; t8++) {
            uint32_t kb0 = __float_as_uint(ksb[ q4   *72 + t8*8 + r]);
            uint32_t kb1 = __float_as_uint(ksb[(q4+4)*72 + t8*8 + r]);
            P[t8][0] = P[t8][1] = P[t8][2] = P[t8][3] = 0.f;
            mma_tf32(P[t8][0], P[t8][1], P[t8][2], P[t8][3],
                     aq0, aq1, aq2, aq3, kb0, kb1);
        }
        #pragma unroll
        for (int t8 = 0; t8 < 8; t8++) {
            P[t8][0] = __expf(P[t8][0] - 12.f); l_lo += P[t8][0];
            P[t8][1] = __expf(P[t8][1] - 12.f); l_lo += P[t8][1];
            P[t8][2] = __expf(P[t8][2] - 12.f); l_hi += P[t8][2];
            P[t8][3] = __expf(P[t8][3] - 12.f); l_hi += P[t8][3];
        }

        // ---- O^T += V * P^T  (V fragments via ldmatrix.x4)
        #pragma unroll
        for (int jc = 0; jc < 8; jc++) {
            float p0a = __shfl_sync(0xffffffffu, P[jc][0], ls0);
            float p0b = __shfl_sync(0xffffffffu, P[jc][1], ls0);
            float p1a = __shfl_sync(0xffffffffu, P[jc][0], ls0 + 2);
            float p1b = __shfl_sync(0xffffffffu, P[jc][1], ls0 + 2);
            uint32_t bn0_0 = __float_as_uint(e ? p0b : p0a);
            uint32_t bn0_1 = __float_as_uint(e ? p1b : p1a);
            float p2a = __shfl_sync(0xffffffffu, P[jc][2], ls0);
            float p2b = __shfl_sync(0xffffffffu, P[jc][3], ls0);
            float p3a = __shfl_sync(0xffffffffu, P[jc][2], ls0 + 2);
            float p3b = __shfl_sync(0xffffffffu, P[jc][3], ls0 + 2);
            uint32_t bn1_0 = __float_as_uint(e ? p2b : p2a);
            uint32_t bn1_1 = __float_as_uint(e ? p3b : p3a);
            #pragma unroll
            for (int mt = 0; mt < 4; mt++) {
                uint32_t a0, a1, a2, a3;
                ldsm_x4(a0, a1, a2, a3, vbase + mt*4352 + jc*32);
                mma_tf32(Oa[mt][0][0], Oa[mt][0][1], Oa[mt][0][2], Oa[mt][0][3],
                         a0, a1, a2, a3, bn0_0, bn0_1);
                mma_tf32(Oa[mt][1][0], Oa[mt][1][1], Oa[mt][1][2], Oa[mt][1][3],
                         a0, a1, a2, a3, bn1_0, bn1_1);
            }
        }
        par ^= 1;
    }

    // ---- reduce l across the quad, stage per-group -----------------------------
    l_lo += __shfl_xor_sync(0xffffffffu, l_lo, 1);
    l_lo += __shfl_xor_sync(0xffffffffu, l_lo, 2);
    l_hi += __shfl_xor_sync(0xffffffffu, l_hi, 1);
    l_hi += __shfl_xor_sync(0xffffffffu, l_hi, 2);
    __syncthreads();
    if (q4 == 0) {
        sm[OFF_L + wg*64 + 16*w4 + r    ] = l_lo;
        sm[OFF_L + wg*64 + 16*w4 + r + 8] = l_hi;
    }
    if (wg == 1) {
        #pragma unroll
        for (int mt = 0; mt < 4; mt++)
            #pragma unroll
            for (int nt = 0; nt < 2; nt++)
                #pragma unroll
                for (int u = 0; u < 4; u++) {
                    int crow = 16*mt + r + 8*(u >> 1);
                    int col  = 16*w4 + 2*q4 + (u & 1) + 8*nt;
                    sm[OFF_OST + crow*68 + col] = Oa[mt][nt][u];
                }
    }
    __syncthreads();

    // ---- group 0 merges: O = (O0 + O1) / (l0 + l1) ----------------------------
    if (wg == 0) {
        float inv[2][2];
        #pragma unroll
        for (int nt = 0; nt < 2; nt++)
            #pragma unroll
            for (int ee = 0; ee < 2; ee++) {
                int iq = 16*w4 + 2*q4 + ee + 8*nt;
                inv[nt][ee] = 1.f / (sm[OFF_L + iq] + sm[OFF_L + 64 + iq]);
            }
        #pragma unroll
        for (int mt = 0; mt < 4; mt++)
            #pragma unroll
            for (int nt = 0; nt < 2; nt++)
                #pragma unroll
                for (int u = 0; u < 4; u++) {
                    int ee = u & 1;
                    int crow = 16*mt + r + 8*(u >> 1);
                    int col  = 16*w4 + 2*q4 + ee + 8*nt;
                    sm[OFF_OFIN + crow*68 + col] =
                        (Oa[mt][nt][u] + sm[OFF_OST + crow*68 + col]) * inv[nt][ee];
                }
    }
    __syncthreads();

    // ---- epilogue --------------------------------------------------------------
    const float gam = gamma_p[0];
    const int h = blockIdx.x;
    float sy = (h + 0.5f)*0.15625f - 0.5f;
    int   y0 = (int)floorf(sy);
    float fy = sy - (float)y0;
    int   y0c = max(y0, 0), y1c = min(y0 + 1, 9);

    #pragma unroll
    for (int kk = 0; kk < 4; kk++) {
        int idx4 = t + 256*kk;
        int c = idx4 >> 4, k4 = (idx4 & 15)*4;
        const float* yr0 = g_y4 + ((size_t)b*CCH + c)*100 + y0c*10;
        const float* yr1 = g_y4 + ((size_t)b*CCH + c)*100 + y1c*10;
        size_t off = ((size_t)b*CCH + c)*NN + i0 + k4;
        float4 xv = *(const float4*)(x + off);
        float4 g4 = *(const float4*)(x + (size_t)b*CCH*NN + i0 + k4);
        float xa[4] = {xv.x, xv.y, xv.z, xv.w};
        float ga[4] = {g4.x, g4.y, g4.z, g4.w};
        float res[4];
        #pragma unroll
        for (int u = 0; u < 4; u++) {
            int wpix = k4 + u;
            float sx = (wpix + 0.5f)*0.15625f - 0.5f;
            int   x0i = (int)floorf(sx);
            float fx = sx - (float)x0i;
            int   x0c = max(x0i, 0), x1c = min(x0i + 1, 9);
            float v00 = yr0[x0c], v01 = yr0[x1c];
            float v10 = yr1[x0c], v11 = yr1[x1c];
            float wv = (1.f-fy)*((1.f-fx)*v00 + fx*v01)
                     +       fy*((1.f-fx)*v10 + fx*v11);
            float gate = 1.f/(1.f + __expf(-ga[u]));
            res[u] = gam*sm[OFF_OFIN + c*68 + k4 + u] + xa[u]*(2.f + wv*gate);
        }
        *(float4*)(out + off) = make_float4(res[0], res[1], res[2], res[3]);
    }
}

// ---------------- launch -------------------------------------------------------
extern "C" void kernel_launch(void* const* d_in, const int* in_sizes, int n_in,
                              void* d_out, int out_size)
{
    const float* x     = (const float*)d_in[0];
    const float* qw    = (const float*)d_in[1];
    const float* qb    = (const float*)d_in[2];
    const float* kw    = (const float*)d_in[3];
    const float* kb    = (const float*)d_in[4];
    const float* vw    = (const float*)d_in[5];
    const float* vb    = (const float*)d_in[6];
    const float* gamma = (const float*)d_in[7];
    const float* w1    = (const float*)d_in[8];
    const float* b1    = (const float*)d_in[9];
    const float* w2    = (const float*)d_in[10];
    const float* b2    = (const float*)d_in[11];
    const float* w3    = (const float*)d_in[12];
    const float* b3    = (const float*)d_in[13];
    float* out = (float*)d_out;

    const int smem = SM_FLTS * 4;
    cudaFuncSetAttribute(flash_tc_kernel,
                         cudaFuncAttributeMaxDynamicSharedMemorySize, smem);

    qkv_kernel<<<dim3(64, BATCH), 256>>>(x, qw, qb, kw, kb, vw, vb, w1, b1);
    softpool_kernel<<<100, 256>>>();
    conv23_kernel<<<64, 256>>>(w2, b2, w3, b3);
    flash_tc_kernel<<<dim3(64, BATCH), 256, smem>>>(x, gamma, out);
}

// round 9
// speedup vs baseline: 4.7883x; 1.4311x over previous
#include <cuda_runtime.h>
#include <cuda_bf16.h>
#include <math.h>
#include <stdint.h>

#define BATCH 4
#define CCH   64
#define NN    4096
#define DQK   8
#define FCH   16

// ---------------- scratch ------------------------------------------------------
__device__ float g_q [BATCH*DQK*NN];            // tf32 bits
__device__ float g_k [BATCH*DQK*NN];            // tf32 bits
__device__ __nv_bfloat16 g_v [BATCH*CCH*NN];    // bf16 [b][c][j]
__device__ float g_e [BATCH*FCH*NN];
__device__ float g_ev[BATCH*FCH*NN];
__device__ float g_y2[BATCH*FCH*400];
__device__ float g_y4[BATCH*CCH*100];

__device__ __forceinline__ float to_tf32(float x){
    uint32_t r;
    asm("cvt.rna.tf32.f32 %0, %1;" : "=r"(r) : "f"(x));
    return __uint_as_float(r);
}
__device__ __forceinline__ uint32_t pack_bf16(float lo, float hi){
    uint32_t d;
    asm("cvt.rn.bf16x2.f32 %0, %1, %2;" : "=r"(d) : "f"(hi), "f"(lo));
    return d;
}
__device__ __forceinline__ void mma_tf32(
    float& d0, float& d1, float& d2, float& d3,
    uint32_t a0, uint32_t a1, uint32_t a2, uint32_t a3,
    uint32_t b0, uint32_t b1)
{
    asm volatile(
        "mma.sync.aligned.m16n8k8.row.col.f32.tf32.tf32.f32 "
        "{%0,%1,%2,%3},{%4,%5,%6,%7},{%8,%9},{%0,%1,%2,%3};"
        : "+f"(d0), "+f"(d1), "+f"(d2), "+f"(d3)
        : "r"(a0), "r"(a1), "r"(a2), "r"(a3), "r"(b0), "r"(b1));
}
__device__ __forceinline__ void mma_bf16(
    float& d0, float& d1, float& d2, float& d3,
    uint32_t a0, uint32_t a1, uint32_t a2, uint32_t a3,
    uint32_t b0, uint32_t b1)
{
    asm volatile(
        "mma.sync.aligned.m16n8k16.row.col.f32.bf16.bf16.f32 "
        "{%0,%1,%2,%3},{%4,%5,%6,%7},{%8,%9},{%0,%1,%2,%3};"
        : "+f"(d0), "+f"(d1), "+f"(d2), "+f"(d3)
        : "r"(a0), "r"(a1), "r"(a2), "r"(a3), "r"(b0), "r"(b1));
}
__device__ __forceinline__ void cpa16(uint32_t dst, const void* src){
    asm volatile("cp.async.cg.shared.global [%0], [%1], 16;"
                 :: "r"(dst), "l"(src));
}
__device__ __forceinline__ void ldsm_x4(uint32_t& a0, uint32_t& a1,
                                        uint32_t& a2, uint32_t& a3, uint32_t addr){
    asm volatile("ldmatrix.sync.aligned.m8n8.x4.shared.b16 {%0,%1,%2,%3}, [%4];"
                 : "=r"(a0), "=r"(a1), "=r"(a2), "=r"(a3) : "r"(addr));
}

// flash smem layout
#define OFF_QS    0                  // f32 idx, 8*72
#define OFF_KS    576                // [wg][par]*576 f32 (tf32)
#define VS_BYTE   11520              // byte offset of V region (f32 idx 2880)
#define VBUF_B    9216               // bytes per V buffer (64 rows * 144B)
#define OFF_L     12096              // f32 idx, [2][64]
#define SM_FLTS   12224              // 48896 B static
#define OFF_OFIN  2880               // f32 idx, 64*68 (reuses V region)
#define OFF_OST   7232               // f32 idx, 64*68

// ---------------- kernel 1: fused 1x1 convs, register-blocked ------------------
__global__ __launch_bounds__(256) void qkv_kernel(
    const float* __restrict__ x,
    const float* __restrict__ qw, const float* __restrict__ qb,
    const float* __restrict__ kw, const float* __restrict__ kb,
    const float* __restrict__ vw, const float* __restrict__ vb,
    const float* __restrict__ w1, const float* __restrict__ b1)
{
    __shared__ float Ws[96*65];
    __shared__ float bs[96];
    __shared__ float xs[64*64];

    const int b  = blockIdx.y;
    const int n0 = blockIdx.x * 64;
    const int t  = threadIdx.x;

    for (int i = t; i < 512;  i += 256) Ws[( 0 + (i>>6))*65 + (i&63)] = qw[i];
    for (int i = t; i < 512;  i += 256) Ws[( 8 + (i>>6))*65 + (i&63)] = kw[i];
    for (int i = t; i < 4096; i += 256) Ws[(16 + (i>>6))*65 + (i&63)] = vw[i];
    for (int i = t; i < 1024; i += 256) Ws[(80 + (i>>6))*65 + (i&63)] = w1[i];
    if (t < 96) {
        float bv;
        if      (t < 8)  bv = qb[t];
        else if (t < 16) bv = kb[t-8];
        else if (t < 80) bv = vb[t-16];
        else             bv = b1[t-80];
        bs[t] = bv;
    }
    #pragma unroll
    for (int kk = 0; kk < 4; kk++) {
        int idx4 = t + 256*kk;
        int c = idx4 >> 4, n4 = idx4 & 15;
        float4 v = *((const float4*)(x + ((size_t)b*CCH + c)*NN + n0) + n4);
        *((float4*)(xs + c*64) + n4) = v;
    }
    __syncthreads();

    const int ng  = t & 15;
    const int ocg = t >> 4;
    float acc[6][4];
    #pragma unroll
    for (int k = 0; k < 6; k++) {
        float bv = bs[ocg*6 + k];
        acc[k][0] = bv; acc[k][1] = bv; acc[k][2] = bv; acc[k][3] = bv;
    }
    #pragma unroll 4
    for (int c = 0; c < 64; c++) {
        float4 xv = *(const float4*)(xs + c*64 + ng*4);
        #pragma unroll
        for (int k = 0; k < 6; k++) {
            float wv = Ws[(ocg*6 + k)*65 + c];
            acc[k][0] += wv*xv.x; acc[k][1] += wv*xv.y;
            acc[k][2] += wv*xv.z; acc[k][3] += wv*xv.w;
        }
    }
    const int gn = n0 + ng*4;
    #pragma unroll
    for (int k = 0; k < 6; k++) {
        int oc = ocg*6 + k;
        if (oc < 16) {
            float4 o = make_float4(to_tf32(acc[k][0]), to_tf32(acc[k][1]),
                                   to_tf32(acc[k][2]), to_tf32(acc[k][3]));
            float* dst = (oc < 8) ? g_q + ((size_t)b*DQK + oc    )*NN + gn
                                  : g_k + ((size_t)b*DQK + oc - 8)*NN + gn;
            *(float4*)dst = o;
        } else if (oc < 80) {
            uint2 pk;
            pk.x = pack_bf16(acc[k][0], acc[k][1]);
            pk.y = pack_bf16(acc[k][2], acc[k][3]);
            *(uint2*)(g_v + ((size_t)b*CCH + oc - 16)*NN + gn) = pk;
        } else {
            size_t o = ((size_t)b*FCH + oc - 80)*NN + gn;
            float e0 = __expf(acc[k][0]), e1 = __expf(acc[k][1]);
            float e2 = __expf(acc[k][2]), e3 = __expf(acc[k][3]);
            *(float4*)(g_e  + o) = make_float4(e0, e1, e2, e3);
            *(float4*)(g_ev + o) = make_float4(e0*acc[k][0], e1*acc[k][1],
                                               e2*acc[k][2], e3*acc[k][3]);
        }
    }
}

// ---------------- kernel 2: softpool -------------------------------------------
__global__ void softpool_kernel()
{
    int idx = blockIdx.x*blockDim.x + threadIdx.x;
    if (idx >= BATCH*FCH*400) return;
    int ox = idx % 20, oy = (idx/20) % 20;
    int c  = (idx/400) % FCH, b = idx/(400*FCH);
    size_t base = ((size_t)b*FCH + c)*NN + (oy*3)*64 + ox*3;
    const float* se  = g_e  + base;
    const float* sev = g_ev + base;
    float num = 0.f, den = 0.f;
    #pragma unroll
    for (int ky = 0; ky < 7; ky++)
        #pragma unroll
        for (int kx = 0; kx < 7; kx++) {
            num += sev[ky*64 + kx];
            den += se [ky*64 + kx];
        }
    g_y2[idx] = num/den;
}

// ---------------- kernel 3: conv2 (redundant) -> conv3(4 oc) + sigmoid ---------
__global__ __launch_bounds__(256) void conv23_kernel(
    const float* __restrict__ w2, const float* __restrict__ b2,
    const float* __restrict__ w3, const float* __restrict__ b3)
{
    __shared__ float y2s[FCH*400];
    __shared__ float y3s[FCH*100];
    const int b  = blockIdx.x >> 4;
    const int og = blockIdx.x & 15;
    const int t  = threadIdx.x;

    for (int o = t; o < FCH*400; o += 256) y2s[o] = g_y2[(size_t)b*FCH*400 + o];
    __syncthreads();

    for (int o = t; o < FCH*100; o += 256) {
        int ox = o % 10, oy = (o/10) % 10, oc = o/100;
        float acc = b2[oc];
        for (int ic = 0; ic < FCH; ic++) {
            const float* src = y2s + ic*400;
            const float* wr  = w2 + (oc*FCH + ic)*9;
            #pragma unroll
            for (int ky = 0; ky < 3; ky++) {
                int iy = oy*2 - 1 + ky;
                if (iy < 0 || iy >= 20) continue;
                #pragma unroll
                for (int kx = 0; kx < 3; kx++) {
                    int ix = ox*2 - 1 + kx;
                    if (ix < 0 || ix >= 20) continue;
                    acc += wr[ky*3+kx] * src[iy*20 + ix];
                }
            }
        }
        y3s[o] = acc;
    }
    __syncthreads();

    for (int o = t; o < 400; o += 256) {
        int ox = o % 10, oy = (o/10) % 10;
        int oc = og*4 + o/100;
        float acc = b3[oc];
        for (int ic = 0; ic < FCH; ic++) {
            const float* src = y3s + ic*100;
            const float* wr  = w3 + (oc*FCH + ic)*9;
            #pragma unroll
            for (int ky = 0; ky < 3; ky++) {
                int iy = oy - 1 + ky;
                if (iy < 0 || iy >= 10) continue;
                #pragma unroll
                for (int kx = 0; kx < 3; kx++) {
                    int ix = ox - 1 + kx;
                    if (ix < 0 || ix >= 10) continue;
                    acc += wr[ky*3+kx] * src[iy*10 + ix];
                }
            }
        }
        g_y4[((size_t)b*CCH + oc)*100 + (o % 100)] = 1.f/(1.f + __expf(-acc));
    }
}

// ---------------- kernel 4: flash — tf32 S, bf16 P·V, no shuffles --------------
__global__ __launch_bounds__(256, 2) void flash_tc_kernel(
    const float* __restrict__ x, const float* __restrict__ gamma_p,
    float* __restrict__ out)
{
    __shared__ __align__(16) float sm[SM_FLTS];
    const int b  = blockIdx.y;
    const int i0 = blockIdx.x * 64;
    const int t  = threadIdx.x;
    const int wg = t >> 7;
    const int tg = t & 127;
    const int w4 = tg >> 5;
    const int lane = t & 31;
    const int r  = lane >> 2;
    const int q4 = lane & 3;
    const int bar = wg + 1;

    for (int kx = t; kx < 512; kx += 256) {
        int d = kx >> 6, i = kx & 63;
        sm[OFF_QS + d*72 + i] = g_q[((size_t)b*DQK + d)*NN + i0 + i];
    }

    // K cp.async (tf32, [d][j] pitch 72 f32): 128 x 16B chunks
    const int kd = tg >> 4, kj4 = tg & 15;
    const float* ksrc = g_k + ((size_t)b*DQK + kd)*NN + wg*2048 + kj4*4;
    uint32_t kdst[2];
    #pragma unroll
    for (int p = 0; p < 2; p++)
        kdst[p] = (uint32_t)__cvta_generic_to_shared(
            sm + OFF_KS + (wg*2 + p)*576 + kd*72 + kj4*4);

    // V cp.async (bf16, [c][j] pitch 144B): 512 x 16B chunks, 4 per thread
    const __nv_bfloat16* vsrc[4];
    uint32_t vdst[2][4];
    #pragma unroll
    for (int kk = 0; kk < 4; kk++) {
        int cc = tg + 128*kk;
        int c = cc >> 3, jj = cc & 7;
        vsrc[kk] = g_v + ((size_t)b*CCH + c)*NN + wg*2048 + jj*8;
        #pragma unroll
        for (int p = 0; p < 2; p++)
            vdst[p][kk] = (uint32_t)__cvta_generic_to_shared(
                (char*)sm + VS_BYTE + (wg*2 + p)*VBUF_B + c*144 + jj*16);
    }

    // ldmatrix.x4 lane offset for B-frags: m0/m1 -> c rows 0-7 (j bytes +0/+16),
    // m2/m3 -> c rows 8-15.
    const uint32_t lm_off = (uint32_t)(((lane & 7) + ((lane >> 4) & 1)*8)*144
                                       + ((lane >> 3) & 1)*16);
    uint32_t vlm[2];
    #pragma unroll
    for (int p = 0; p < 2; p++)
        vlm[p] = (uint32_t)__cvta_generic_to_shared(
                     (char*)sm + VS_BYTE + (wg*2 + p)*VBUF_B) + lm_off;

    cpa16(kdst[0], ksrc);
    #pragma unroll
    for (int kk = 0; kk < 4; kk++) cpa16(vdst[0][kk], vsrc[kk]);
    asm volatile("cp.async.commit_group;");

    __syncthreads();
    const uint32_t aq0 = __float_as_uint(sm[OFF_QS +  q4   *72 + 16*w4 + r    ]);
    const uint32_t aq1 = __float_as_uint(sm[OFF_QS +  q4   *72 + 16*w4 + r + 8]);
    const uint32_t aq2 = __float_as_uint(sm[OFF_QS + (q4+4)*72 + 16*w4 + r    ]);
    const uint32_t aq3 = __float_as_uint(sm[OFF_QS + (q4+4)*72 + 16*w4 + r + 8]);

    float Oa[8][4];                 // [nc][u]: O[i=r(+8)][c = nc*8 + 2q4(+1)]
    #pragma unroll
    for (int nc = 0; nc < 8; nc++)
        #pragma unroll
        for (int u = 0; u < 4; u++) Oa[nc][u] = 0.f;
    float l_lo = 0.f, l_hi = 0.f;
    int par = 0;

    for (int it = 0; it < 32; ++it) {
        asm volatile("bar.sync %0, 128;" :: "r"(bar));
        if (it + 1 < 32) {
            int off = (it + 1)*64;
            cpa16(kdst[par^1], ksrc + off);
            #pragma unroll
            for (int kk = 0; kk < 4; kk++) cpa16(vdst[par^1][kk], vsrc[kk] + off);
        }
        asm volatile("cp.async.commit_group;");
        asm volatile("cp.async.wait_group 1;");
        asm volatile("bar.sync %0, 128;" :: "r"(bar));

        const float* ksb = sm + OFF_KS + (wg*2 + par)*576;
        const uint32_t vb = vlm[par];

        // ---- S = Q*K (tf32), P = exp(S - 12)
        float P[8][4];
        #pragma unroll
        for (int t8 = 0; t8 < 8; t8++) {
            uint32_t kb0 = __float_as_uint(ksb[ q4   *72 + t8*8 + r]);
            uint32_t kb1 = __float_as_uint(ksb[(q4+4)*72 + t8*8 + r]);
            P[t8][0] = P[t8][1] = P[t8][2] = P[t8][3] = 0.f;
            mma_tf32(P[t8][0], P[t8][1], P[t8][2], P[t8][3],
                     aq0, aq1, aq2, aq3, kb0, kb1);
        }
        uint32_t Pbl[8], Pbh[8];
        #pragma unroll
        for (int t8 = 0; t8 < 8; t8++) {
            P[t8][0] = __expf(P[t8][0] - 12.f); l_lo += P[t8][0];
            P[t8][1] = __expf(P[t8][1] - 12.f); l_lo += P[t8][1];
            P[t8][2] = __expf(P[t8][2] - 12.f); l_hi += P[t8][2];
            P[t8][3] = __expf(P[t8][3] - 12.f); l_hi += P[t8][3];
            Pbl[t8] = pack_bf16(P[t8][0], P[t8][1]);   // row r
            Pbh[t8] = pack_bf16(P[t8][2], P[t8][3]);   // row r+8
        }

        // ---- O += P·V (bf16 m16n8k16); B-frags via non-trans ldmatrix.x4
        #pragma unroll
        for (int kt = 0; kt < 4; kt++) {
            uint32_t a0 = Pbl[2*kt],   a1 = Pbh[2*kt];
            uint32_t a2 = Pbl[2*kt+1], a3 = Pbh[2*kt+1];
            #pragma unroll
            for (int ncp = 0; ncp < 4; ncp++) {
                uint32_t b0, b1, b2, b3;
                ldsm_x4(b0, b1, b2, b3, vb + ncp*2304 + kt*32);
                mma_bf16(Oa[2*ncp][0], Oa[2*ncp][1], Oa[2*ncp][2], Oa[2*ncp][3],
                         a0, a1, a2, a3, b0, b1);
                mma_bf16(Oa[2*ncp+1][0], Oa[2*ncp+1][1],
                         Oa[2*ncp+1][2], Oa[2*ncp+1][3],
                         a0, a1, a2, a3, b2, b3);
            }
        }
        par ^= 1;
    }

    // ---- reduce l across the quad, stage per-group -----------------------------
    l_lo += __shfl_xor_sync(0xffffffffu, l_lo, 1);
    l_lo += __shfl_xor_sync(0xffffffffu, l_lo, 2);
    l_hi += __shfl_xor_sync(0xffffffffu, l_hi, 1);
    l_hi += __shfl_xor_sync(0xffffffffu, l_hi, 2);
    __syncthreads();
    if (q4 == 0) {
        sm[OFF_L + wg*64 + 16*w4 + r    ] = l_lo;
        sm[OFF_L + wg*64 + 16*w4 + r + 8] = l_hi;
    }
    if (wg == 1) {
        #pragma unroll
        for (int nc = 0; nc < 8; nc++)
            #pragma unroll
            for (int u = 0; u < 4; u++) {
                int c  = nc*8 + 2*q4 + (u & 1);
                int il = 16*w4 + r + 8*(u >> 1);
                sm[OFF_OST + c*68 + il] = Oa[nc][u];
            }
    }
    __syncthreads();

    // ---- group 0 merges: O = (O0 + O1) / (l0 + l1) ----------------------------
    if (wg == 0) {
        int iqa = 16*w4 + r;
        float inv0 = 1.f / (sm[OFF_L + iqa    ] + sm[OFF_L + 64 + iqa    ]);
        float inv1 = 1.f / (sm[OFF_L + iqa + 8] + sm[OFF_L + 64 + iqa + 8]);
        #pragma unroll
        for (int nc = 0; nc < 8; nc++)
            #pragma unroll
            for (int u = 0; u < 4; u++) {
                int c  = nc*8 + 2*q4 + (u & 1);
                int il = 16*w4 + r + 8*(u >> 1);
                sm[OFF_OFIN + c*68 + il] =
                    (Oa[nc][u] + sm[OFF_OST + c*68 + il]) * ((u >> 1) ? inv1 : inv0);
            }
    }
    __syncthreads();

    // ---- epilogue --------------------------------------------------------------
    const float gam = gamma_p[0];
    const int h = blockIdx.x;
    float sy = (h + 0.5f)*0.15625f - 0.5f;
    int   y0 = (int)floorf(sy);
    float fy = sy - (float)y0;
    int   y0c = max(y0, 0), y1c = min(y0 + 1, 9);

    #pragma unroll
    for (int kk = 0; kk < 4; kk++) {
        int idx4 = t + 256*kk;
        int c = idx4 >> 4, k4 = (idx4 & 15)*4;
        const float* yr0 = g_y4 + ((size_t)b*CCH + c)*100 + y0c*10;
        const float* yr1 = g_y4 + ((size_t)b*CCH + c)*100 + y1c*10;
        size_t off = ((size_t)b*CCH + c)*NN + i0 + k4;
        float4 xv = *(const float4*)(x + off);
        float4 g4 = *(const float4*)(x + (size_t)b*CCH*NN + i0 + k4);
        float xa[4] = {xv.x, xv.y, xv.z, xv.w};
        float ga[4] = {g4.x, g4.y, g4.z, g4.w};
        float res[4];
        #pragma unroll
        for (int u = 0; u < 4; u++) {
            int wpix = k4 + u;
            float sx = (wpix + 0.5f)*0.15625f - 0.5f;
            int   x0i = (int)floorf(sx);
            float fx = sx - (float)x0i;
            int   x0c = max(x0i, 0), x1c = min(x0i + 1, 9);
            float v00 = yr0[x0c], v01 = yr0[x1c];
            float v10 = yr1[x0c], v11 = yr1[x1c];
            float wv = (1.f-fy)*((1.f-fx)*v00 + fx*v01)
                     +       fy*((1.f-fx)*v10 + fx*v11);
            float gate = 1.f/(1.f + __expf(-ga[u]));
            res[u] = gam*sm[OFF_OFIN + c*68 + k4 + u] + xa[u]*(2.f + wv*gate);
        }
        *(float4*)(out + off) = make_float4(res[0], res[1], res[2], res[3]);
    }
}

// ---------------- launch -------------------------------------------------------
extern "C" void kernel_launch(void* const* d_in, const int* in_sizes, int n_in,
                              void* d_out, int out_size)
{
    const float* x     = (const float*)d_in[0];
    const float* qw    = (const float*)d_in[1];
    const float* qb    = (const float*)d_in[2];
    const float* kw    = (const float*)d_in[3];
    const float* kb    = (const float*)d_in[4];
    const float* vw    = (const float*)d_in[5];
    const float* vb    = (const float*)d_in[6];
    const float* gamma = (const float*)d_in[7];
    const float* w1    = (const float*)d_in[8];
    const float* b1    = (const float*)d_in[9];
    const float* w2    = (const float*)d_in[10];
    const float* b2    = (const float*)d_in[11];
    const float* w3    = (const float*)d_in[12];
    const float* b3    = (const float*)d_in[13];
    float* out = (float*)d_out;

    qkv_kernel<<<dim3(64, BATCH), 256>>>(x, qw, qb, kw, kb, vw, vb, w1, b1);
    softpool_kernel<<<100, 256>>>();
    conv23_kernel<<<64, 256>>>(w2, b2, w3, b3);
    flash_tc_kernel<<<dim3(64, BATCH), 256>>>(x, gamma, out);
}